// round 4
// baseline (speedup 1.0000x reference)
#include <cuda_runtime.h>
#include <cuda_bf16.h>
#include <math.h>
#include <stdint.h>

// ---------------------------------------------------------------- dims
#define BSZ 4
#define SEQ 4096
#define DM  512
#define NROWS (BSZ * SEQ)                 // 16384
#define NTH 256
#define BM 128
#define BN 256
#define BK 32
#define SOFTMAX_SCALE 0.04419417382415922f

// smem stage layout (bf16 tiles, 64-byte rows, SW64 swizzle)
#define SA_H 0
#define SA_L 8192
#define SB_H 16384
#define SB_L 32768
#define STAGE 49152
#define NSTAGE 3
#define SMEM_TOTAL (NSTAGE * STAGE)       // 147456 bytes

#define SW64(o) ((uint32_t)(o) ^ ((((uint32_t)(o)) >> 3) & 0x30u))

// ---------------------------------------------------------------- scratch
__device__ __nv_bfloat16 g_xh[(size_t)NROWS * DM];
__device__ __nv_bfloat16 g_xl[(size_t)NROWS * DM];
__device__ __nv_bfloat16 g_Wh[3 * DM * DM];
__device__ __nv_bfloat16 g_Wl[3 * DM * DM];
__device__ __nv_bfloat16 g_Qh[(size_t)NROWS * DM];   // pre-scaled by 1/sqrt(D)
__device__ __nv_bfloat16 g_Ql[(size_t)NROWS * DM];
__device__ __nv_bfloat16 g_Kh[(size_t)NROWS * DM];
__device__ __nv_bfloat16 g_Kl[(size_t)NROWS * DM];
__device__ __nv_bfloat16 g_Vth[(size_t)BSZ * DM * SEQ];  // V^T [b][d][s]
__device__ __nv_bfloat16 g_Vtl[(size_t)BSZ * DM * SEQ];
__device__ __nv_bfloat16 g_Ph[(size_t)BSZ * SEQ * SEQ];  // probs hi/lo
__device__ __nv_bfloat16 g_Pl[(size_t)BSZ * SEQ * SEQ];

// ---------------------------------------------------------------- helpers
__device__ __forceinline__ uint32_t smem_u32(const void* p) {
    return (uint32_t)__cvta_generic_to_shared(p);
}
__device__ __forceinline__ void ldmx4(uint32_t r[4], uint32_t addr) {
    asm volatile("ldmatrix.sync.aligned.m8n8.x4.shared.b16 {%0,%1,%2,%3}, [%4];"
                 : "=r"(r[0]), "=r"(r[1]), "=r"(r[2]), "=r"(r[3]) : "r"(addr));
}
__device__ __forceinline__ void mma16816(float d[4], const uint32_t a[4],
                                         uint32_t b0, uint32_t b1) {
    asm volatile("mma.sync.aligned.m16n8k16.row.col.f32.bf16.bf16.f32 "
                 "{%0,%1,%2,%3}, {%4,%5,%6,%7}, {%8,%9}, {%0,%1,%2,%3};"
                 : "+f"(d[0]), "+f"(d[1]), "+f"(d[2]), "+f"(d[3])
                 : "r"(a[0]), "r"(a[1]), "r"(a[2]), "r"(a[3]), "r"(b0), "r"(b1));
}
__device__ __forceinline__ void cpasync16(uint32_t dst, const void* src) {
    asm volatile("cp.async.cg.shared.global [%0], [%1], 16;" :: "r"(dst), "l"(src));
}
#define CP_COMMIT() asm volatile("cp.async.commit_group;")
#define CP_WAIT(N)  asm volatile("cp.async.wait_group %0;" :: "n"(N))

__device__ __forceinline__ void split_bf16(float v, uint16_t& h, uint16_t& l) {
    __nv_bfloat16 hb = __float2bfloat16(v);
    float r = v - __bfloat162float(hb);
    h = __bfloat16_as_ushort(hb);
    l = __bfloat16_as_ushort(__float2bfloat16(r));
}

// 128x32 bf16 tile -> swizzled smem (2 x 16B per thread)
__device__ __forceinline__ void load_tile128(uint32_t sdst, const __nv_bfloat16* g,
                                             size_t ld, int t) {
    #pragma unroll
    for (int j = 0; j < 2; j++) {
        int i = t + j * NTH;
        int row = i >> 2, c = i & 3;
        cpasync16(sdst + SW64((row << 6) + (c << 4)), g + (size_t)row * ld + c * 8);
    }
}
// 256x32 bf16 tile -> swizzled smem (4 x 16B per thread)
__device__ __forceinline__ void load_tile256(uint32_t sdst, const __nv_bfloat16* g,
                                             size_t ld, int t) {
    #pragma unroll
    for (int j = 0; j < 4; j++) {
        int i = t + j * NTH;
        int row = i >> 2, c = i & 3;
        cpasync16(sdst + SW64((row << 6) + (c << 4)), g + (size_t)row * ld + c * 8);
    }
}
__device__ __forceinline__ void load_chunk(uint32_t s,
                                           const __nv_bfloat16* Ah, const __nv_bfloat16* Al,
                                           const __nv_bfloat16* Bh, const __nv_bfloat16* Bl,
                                           size_t ldA, size_t ldB, int k0, int t) {
    load_tile128(s + SA_H, Ah + k0, ldA, t);
    load_tile128(s + SA_L, Al + k0, ldA, t);
    load_tile256(s + SB_H, Bh + k0, ldB, t);
    load_tile256(s + SB_L, Bl + k0, ldB, t);
}

// one BK=32 chunk: acc += Ah*Bh + Ah*Bl + Al*Bh  (warp tile 32x128)
__device__ __forceinline__ void compute_stage(uint32_t s, int wr, int wc, int lane,
                                              float acc[2][16][4]) {
    #pragma unroll
    for (int ks = 0; ks < 2; ks++) {
        const int k0 = ks * 16;
        uint32_t ah[2][4], al[2][4];
        const int arow = wr * 32 + (lane & 15);
        const int acol = k0 + ((lane >> 4) << 3);
        #pragma unroll
        for (int mi = 0; mi < 2; mi++) {
            uint32_t off = SW64(((arow + mi * 16) << 6) + (acol << 1));
            ldmx4(ah[mi], s + SA_H + off);
            ldmx4(al[mi], s + SA_L + off);
        }
        const int brow = wc * 128 + ((lane >> 4) << 3) + (lane & 7);
        const int bcol = k0 + (((lane >> 3) & 1) << 3);
        #pragma unroll
        for (int p = 0; p < 8; p++) {
            uint32_t bh[4], bl[4];
            uint32_t off = SW64(((brow + p * 16) << 6) + (bcol << 1));
            ldmx4(bh, s + SB_H + off);
            ldmx4(bl, s + SB_L + off);
            #pragma unroll
            for (int mi = 0; mi < 2; mi++) {
                mma16816(acc[mi][2 * p],     ah[mi], bh[0], bh[1]);
                mma16816(acc[mi][2 * p + 1], ah[mi], bh[2], bh[3]);
                mma16816(acc[mi][2 * p],     ah[mi], bl[0], bl[1]);
                mma16816(acc[mi][2 * p + 1], ah[mi], bl[2], bl[3]);
                mma16816(acc[mi][2 * p],     al[mi], bh[0], bh[1]);
                mma16816(acc[mi][2 * p + 1], al[mi], bh[2], bh[3]);
            }
        }
    }
}

// 3-stage pipeline, one barrier per chunk, uniform one-commit-per-chunk
#define GEMM_PIPELINE(Ah, Al, Bh, Bl, ldA, ldB, nch)                              \
    do {                                                                          \
        load_chunk(sb, Ah, Al, Bh, Bl, ldA, ldB, 0, t);                           \
        CP_COMMIT();                                                              \
        if ((nch) > 1) load_chunk(sb + STAGE, Ah, Al, Bh, Bl, ldA, ldB, BK, t);   \
        CP_COMMIT();                                                              \
        for (int c = 0; c < (nch); c++) {                                         \
            CP_WAIT(1);                                                           \
            __syncthreads();                                                      \
            if (c + 2 < (nch))                                                    \
                load_chunk(sb + ((c + 2) % NSTAGE) * STAGE, Ah, Al, Bh, Bl,       \
                           ldA, ldB, (c + 2) * BK, t);                            \
            CP_COMMIT();                                                          \
            compute_stage(sb + (c % NSTAGE) * STAGE, wr, wc, lane, acc);          \
        }                                                                         \
    } while (0)

// ---------------------------------------------------------------- split kernel
__global__ __launch_bounds__(NTH)
void split_kernel(const float* __restrict__ src, __nv_bfloat16* __restrict__ h,
                  __nv_bfloat16* __restrict__ l, int n4) {
    int i = blockIdx.x * NTH + threadIdx.x;
    if (i >= n4) return;
    float4 v = reinterpret_cast<const float4*>(src)[i];
    uint16_t h0, h1, h2, h3, l0, l1, l2, l3;
    split_bf16(v.x, h0, l0); split_bf16(v.y, h1, l1);
    split_bf16(v.z, h2, l2); split_bf16(v.w, h3, l3);
    reinterpret_cast<uint2*>(h)[i] =
        make_uint2((uint32_t)h0 | ((uint32_t)h1 << 16), (uint32_t)h2 | ((uint32_t)h3 << 16));
    reinterpret_cast<uint2*>(l)[i] =
        make_uint2((uint32_t)l0 | ((uint32_t)l1 << 16), (uint32_t)l2 | ((uint32_t)l3 << 16));
}

// ---------------------------------------------------------------- kernel: QKV
__global__ __launch_bounds__(NTH, 1)
void qkv_kernel() {
    extern __shared__ __align__(128) char smem[];
    const uint32_t sb = smem_u32(smem);
    const int t = threadIdx.x, wid = t >> 5, lane = t & 31;
    const int wr = wid & 3, wc = wid >> 2;
    const int which = blockIdx.z;
    const int m0 = blockIdx.y * BM;      // global row (b*SEQ+s)
    const int n0 = blockIdx.x * BN;

    const __nv_bfloat16* Ah = g_xh + (size_t)m0 * DM;
    const __nv_bfloat16* Al = g_xl + (size_t)m0 * DM;
    const __nv_bfloat16* Bh = g_Wh + (size_t)which * DM * DM + (size_t)n0 * DM;
    const __nv_bfloat16* Bl = g_Wl + (size_t)which * DM * DM + (size_t)n0 * DM;

    float acc[2][16][4];
    #pragma unroll
    for (int a = 0; a < 2; a++)
        #pragma unroll
        for (int b = 0; b < 16; b++)
            #pragma unroll
            for (int r = 0; r < 4; r++) acc[a][b][r] = 0.0f;

    GEMM_PIPELINE(Ah, Al, Bh, Bl, DM, DM, DM / BK);

    if (which < 2) {
        __nv_bfloat16* Dh = (which == 0) ? g_Qh : g_Kh;
        __nv_bfloat16* Dl = (which == 0) ? g_Ql : g_Kl;
        const float sc = (which == 0) ? SOFTMAX_SCALE : 1.0f;
        #pragma unroll
        for (int mi = 0; mi < 2; mi++) {
            #pragma unroll
            for (int ni = 0; ni < 16; ni++) {
                int row = m0 + wr * 32 + mi * 16 + (lane >> 2);
                int col = n0 + wc * 128 + ni * 8 + ((lane & 3) << 1);
                uint16_t h0, h1, l0, l1;
                split_bf16(acc[mi][ni][0] * sc, h0, l0);
                split_bf16(acc[mi][ni][1] * sc, h1, l1);
                *reinterpret_cast<uint32_t*>(&Dh[(size_t)row * DM + col]) =
                    (uint32_t)h0 | ((uint32_t)h1 << 16);
                *reinterpret_cast<uint32_t*>(&Dl[(size_t)row * DM + col]) =
                    (uint32_t)l0 | ((uint32_t)l1 << 16);
                split_bf16(acc[mi][ni][2] * sc, h0, l0);
                split_bf16(acc[mi][ni][3] * sc, h1, l1);
                *reinterpret_cast<uint32_t*>(&Dh[(size_t)(row + 8) * DM + col]) =
                    (uint32_t)h0 | ((uint32_t)h1 << 16);
                *reinterpret_cast<uint32_t*>(&Dl[(size_t)(row + 8) * DM + col]) =
                    (uint32_t)l0 | ((uint32_t)l1 << 16);
            }
        }
    } else {
        // V: transpose through smem (XOR-skewed), write V^T hi/lo coalesced
        __syncthreads();
        #pragma unroll
        for (int mi = 0; mi < 2; mi++) {
            #pragma unroll
            for (int ni = 0; ni < 16; ni++) {
                #pragma unroll
                for (int r = 0; r < 4; r++) {
                    int srow = wr * 32 + mi * 16 + (lane >> 2) + ((r >> 1) << 3);
                    int dcol = wc * 128 + ni * 8 + ((lane & 3) << 1) + (r & 1);
                    uint32_t addr = (uint32_t)(dcol * 256 + srow * 2) ^ (((uint32_t)dcol & 7) << 4);
                    uint16_t h, l;
                    split_bf16(acc[mi][ni][r], h, l);
                    *reinterpret_cast<uint16_t*>(smem + addr) = h;
                    *reinterpret_cast<uint16_t*>(smem + 65536 + addr) = l;
                }
            }
        }
        __syncthreads();
        const int b = m0 >> 12, s0 = m0 & (SEQ - 1);
        // warp w handles d rows [w*32, w*32+32); 2 rows per rep, half-warp per row
        #pragma unroll
        for (int rep = 0; rep < 16; rep++) {
            int d = wid * 32 + rep * 2 + (lane >> 4);
            int q = lane & 15;
            uint32_t addr = (uint32_t)(d * 256 + q * 16) ^ (((uint32_t)d & 7) << 4);
            uint4 vh = *reinterpret_cast<const uint4*>(smem + addr);
            uint4 vl = *reinterpret_cast<const uint4*>(smem + 65536 + addr);
            size_t o = ((size_t)b * DM + n0 + d) * SEQ + s0 + q * 8;
            *reinterpret_cast<uint4*>(g_Vth + o) = vh;
            *reinterpret_cast<uint4*>(g_Vtl + o) = vl;
        }
    }
}

// ---------------------------------------------------------------- kernel: scores
__global__ __launch_bounds__(NTH, 1)
void scores_kernel(float* __restrict__ att) {
    const int kt = blockIdx.x, qt = blockIdx.y;
    if (2 * kt > qt) return;             // tile fully masked
    const int b = blockIdx.z;

    extern __shared__ __align__(128) char smem[];
    const uint32_t sb = smem_u32(smem);
    const int t = threadIdx.x, wid = t >> 5, lane = t & 31;
    const int wr = wid & 3, wc = wid >> 2;

    const size_t qr = ((size_t)b * SEQ + qt * BM) * DM;
    const size_t kr = ((size_t)b * SEQ + kt * BN) * DM;
    const __nv_bfloat16* Ah = g_Qh + qr;
    const __nv_bfloat16* Al = g_Ql + qr;
    const __nv_bfloat16* Bh = g_Kh + kr;
    const __nv_bfloat16* Bl = g_Kl + kr;

    float acc[2][16][4];
    #pragma unroll
    for (int a = 0; a < 2; a++)
        #pragma unroll
        for (int c = 0; c < 16; c++)
            #pragma unroll
            for (int r = 0; r < 4; r++) acc[a][c][r] = 0.0f;

    GEMM_PIPELINE(Ah, Al, Bh, Bl, DM, DM, DM / BK);

    float* attb = att + (size_t)b * SEQ * SEQ;
    #pragma unroll
    for (int mi = 0; mi < 2; mi++) {
        #pragma unroll
        for (int ni = 0; ni < 16; ni++) {
            int row = qt * BM + wr * 32 + mi * 16 + (lane >> 2);
            int col = kt * BN + wc * 128 + ni * 8 + ((lane & 3) << 1);
            *reinterpret_cast<float2*>(&attb[(size_t)row * SEQ + col]) =
                make_float2(acc[mi][ni][0], acc[mi][ni][1]);
            *reinterpret_cast<float2*>(&attb[(size_t)(row + 8) * SEQ + col]) =
                make_float2(acc[mi][ni][2], acc[mi][ni][3]);
        }
    }
}

// ---------------------------------------------------------------- kernel: softmax
__global__ __launch_bounds__(NTH)
void softmax_kernel(float* __restrict__ att) {
    const int rr = blockIdx.x;
    const int b = rr >> 12;
    const int q = rr & (SEQ - 1);
    float* __restrict__ row = att + (size_t)b * SEQ * SEQ + (size_t)q * SEQ;
    __nv_bfloat16* __restrict__ ph = g_Ph + (size_t)b * SEQ * SEQ + (size_t)q * SEQ;
    __nv_bfloat16* __restrict__ pl = g_Pl + (size_t)b * SEQ * SEQ + (size_t)q * SEQ;
    const int L = q + 1;
    const int jmax = ((q >> 7) + 1) << 7;   // pad to 128 for the AV gemm

    __shared__ float sm[SEQ];
    __shared__ float red[NTH];
    const int t = threadIdx.x;

    float mx = -INFINITY;
    for (int j = t; j < L; j += NTH) {
        float v = row[j];
        sm[j] = v;
        mx = fmaxf(mx, v);
    }
    red[t] = mx;
    __syncthreads();
    #pragma unroll
    for (int s = NTH / 2; s > 0; s >>= 1) {
        if (t < s) red[t] = fmaxf(red[t], red[t + s]);
        __syncthreads();
    }
    const float rowmax = red[0];
    __syncthreads();

    float sum = 0.0f;
    for (int j = t; j < L; j += NTH) {
        float e = __expf(sm[j] - rowmax);
        sm[j] = e;
        sum += e;
    }
    red[t] = sum;
    __syncthreads();
    #pragma unroll
    for (int s = NTH / 2; s > 0; s >>= 1) {
        if (t < s) red[t] += red[t + s];
        __syncthreads();
    }
    const float inv = 1.0f / red[0];

    for (int j = t; j < SEQ; j += NTH) {
        float v = (j < L) ? sm[j] * inv : 0.0f;
        row[j] = v;
        if (j < jmax) {
            uint16_t h, l;
            split_bf16(v, h, l);
            ph[j] = __ushort_as_bfloat16(h);
            pl[j] = __ushort_as_bfloat16(l);
        }
    }
}

// ---------------------------------------------------------------- kernel: AV + residual
__global__ __launch_bounds__(NTH, 1)
void av_kernel(const float* __restrict__ x, float* __restrict__ out) {
    const int b = blockIdx.z;
    const int qt = blockIdx.y;
    const int n0 = blockIdx.x * BN;
    const int m0 = qt * BM;              // batch-local q row

    extern __shared__ __align__(128) char smem[];
    const uint32_t sb = smem_u32(smem);
    const int t = threadIdx.x, wid = t >> 5, lane = t & 31;
    const int wr = wid & 3, wc = wid >> 2;

    const size_t pr = ((size_t)b * SEQ + m0) * SEQ;
    const size_t vr = ((size_t)b * DM + n0) * SEQ;
    const __nv_bfloat16* Ah = g_Ph + pr;
    const __nv_bfloat16* Al = g_Pl + pr;
    const __nv_bfloat16* Bh = g_Vth + vr;
    const __nv_bfloat16* Bl = g_Vtl + vr;

    float acc[2][16][4];
    #pragma unroll
    for (int a = 0; a < 2; a++)
        #pragma unroll
        for (int c = 0; c < 16; c++)
            #pragma unroll
            for (int r = 0; r < 4; r++) acc[a][c][r] = 0.0f;

    const int nch = ((qt + 1) * BM) / BK;   // causal truncation

    GEMM_PIPELINE(Ah, Al, Bh, Bl, SEQ, SEQ, nch);

    #pragma unroll
    for (int mi = 0; mi < 2; mi++) {
        #pragma unroll
        for (int ni = 0; ni < 16; ni++) {
            int row = m0 + wr * 32 + mi * 16 + (lane >> 2);
            int col = n0 + wc * 128 + ni * 8 + ((lane & 3) << 1);
            size_t base = ((size_t)b * SEQ + row) * DM + col;
            float2 xv = *reinterpret_cast<const float2*>(&x[base]);
            *reinterpret_cast<float2*>(&out[base]) =
                make_float2(acc[mi][ni][0] + xv.x, acc[mi][ni][1] + xv.y);
            size_t base8 = base + (size_t)8 * DM;
            float2 xv8 = *reinterpret_cast<const float2*>(&x[base8]);
            *reinterpret_cast<float2*>(&out[base8]) =
                make_float2(acc[mi][ni][2] + xv8.x, acc[mi][ni][3] + xv8.y);
        }
    }
}

// ---------------------------------------------------------------- launch
extern "C" void kernel_launch(void* const* d_in, const int* in_sizes, int n_in,
                              void* d_out, int out_size) {
    const float* x  = (const float*)d_in[0];
    const float* WQ = (const float*)d_in[1];
    const float* WK = (const float*)d_in[2];
    const float* WV = (const float*)d_in[3];

    float* out = (float*)d_out;                   // [B,S,D]
    float* att = out + (size_t)BSZ * SEQ * DM;    // [B,S,S]

    cudaFuncSetAttribute(qkv_kernel,    cudaFuncAttributeMaxDynamicSharedMemorySize, SMEM_TOTAL);
    cudaFuncSetAttribute(scores_kernel, cudaFuncAttributeMaxDynamicSharedMemorySize, SMEM_TOTAL);
    cudaFuncSetAttribute(av_kernel,     cudaFuncAttributeMaxDynamicSharedMemorySize, SMEM_TOTAL);

    __nv_bfloat16 *xh, *xl, *Wh, *Wl;
    cudaGetSymbolAddress((void**)&xh, g_xh);
    cudaGetSymbolAddress((void**)&xl, g_xl);
    cudaGetSymbolAddress((void**)&Wh, g_Wh);
    cudaGetSymbolAddress((void**)&Wl, g_Wl);

    // 0) split fp32 inputs into bf16 hi/lo
    split_kernel<<<(NROWS * DM / 4 + NTH - 1) / NTH, NTH>>>(x, xh, xl, NROWS * DM / 4);
    split_kernel<<<(DM * DM / 4 + NTH - 1) / NTH, NTH>>>(WQ, Wh, Wl, DM * DM / 4);
    split_kernel<<<(DM * DM / 4 + NTH - 1) / NTH, NTH>>>(WK, Wh + DM * DM, Wl + DM * DM, DM * DM / 4);
    split_kernel<<<(DM * DM / 4 + NTH - 1) / NTH, NTH>>>(WV, Wh + 2 * DM * DM, Wl + 2 * DM * DM, DM * DM / 4);

    // 1) QKV projections (Q pre-scaled; V transposed)
    dim3 g1(DM / BN, NROWS / BM, 3);
    qkv_kernel<<<g1, NTH, SMEM_TOTAL>>>();

    // 2) causal scores (fp32) into attention output region
    dim3 g2(SEQ / BN, SEQ / BM, BSZ);
    scores_kernel<<<g2, NTH, SMEM_TOTAL>>>(att);

    // 3) softmax: fp32 probs to d_out, bf16 hi/lo probs to scratch
    softmax_kernel<<<NROWS, NTH>>>(att);

    // 4) O = P @ V + x
    dim3 g4(DM / BN, SEQ / BM, BSZ);
    av_kernel<<<g4, NTH, SMEM_TOTAL>>>(x, out);
}

// round 5
// speedup vs baseline: 1.1245x; 1.1245x over previous
#include <cuda_runtime.h>
#include <cuda_bf16.h>
#include <math.h>
#include <stdint.h>

// ---------------------------------------------------------------- dims
#define BSZ 4
#define SEQ 4096
#define DM  512
#define NROWS (BSZ * SEQ)                 // 16384
#define NTH 256
#define BM 128
#define BN 128
#define BK 32
#define SOFTMAX_SCALE 0.04419417382415922f

// smem stage layout (bf16 tiles, 64-byte rows, SW64 swizzle)
#define SA_H 0
#define SA_L 8192
#define SB_H 16384
#define SB_L 24576
#define STAGE 32768
#define NSTAGE 3
#define SMEM_TOTAL (NSTAGE * STAGE)       // 98304 bytes -> 2 CTAs/SM

#define SW64(o) ((uint32_t)(o) ^ ((((uint32_t)(o)) >> 3) & 0x30u))

// ---------------------------------------------------------------- scratch
__device__ __nv_bfloat16 g_xh[(size_t)NROWS * DM];
__device__ __nv_bfloat16 g_xl[(size_t)NROWS * DM];
__device__ __nv_bfloat16 g_Wh[3 * DM * DM];
__device__ __nv_bfloat16 g_Wl[3 * DM * DM];
__device__ __nv_bfloat16 g_Qh[(size_t)NROWS * DM];   // pre-scaled by 1/sqrt(D)
__device__ __nv_bfloat16 g_Ql[(size_t)NROWS * DM];
__device__ __nv_bfloat16 g_Kh[(size_t)NROWS * DM];
__device__ __nv_bfloat16 g_Kl[(size_t)NROWS * DM];
__device__ __nv_bfloat16 g_Vth[(size_t)BSZ * DM * SEQ];  // V^T [b][d][s]
__device__ __nv_bfloat16 g_Vtl[(size_t)BSZ * DM * SEQ];
__device__ __nv_bfloat16 g_Ph[(size_t)BSZ * SEQ * SEQ];  // probs hi/lo
__device__ __nv_bfloat16 g_Pl[(size_t)BSZ * SEQ * SEQ];

// ---------------------------------------------------------------- helpers
__device__ __forceinline__ uint32_t smem_u32(const void* p) {
    return (uint32_t)__cvta_generic_to_shared(p);
}
__device__ __forceinline__ void ldmx4(uint32_t r[4], uint32_t addr) {
    asm volatile("ldmatrix.sync.aligned.m8n8.x4.shared.b16 {%0,%1,%2,%3}, [%4];"
                 : "=r"(r[0]), "=r"(r[1]), "=r"(r[2]), "=r"(r[3]) : "r"(addr));
}
__device__ __forceinline__ void mma16816(float d[4], const uint32_t a[4],
                                         uint32_t b0, uint32_t b1) {
    asm volatile("mma.sync.aligned.m16n8k16.row.col.f32.bf16.bf16.f32 "
                 "{%0,%1,%2,%3}, {%4,%5,%6,%7}, {%8,%9}, {%0,%1,%2,%3};"
                 : "+f"(d[0]), "+f"(d[1]), "+f"(d[2]), "+f"(d[3])
                 : "r"(a[0]), "r"(a[1]), "r"(a[2]), "r"(a[3]), "r"(b0), "r"(b1));
}
__device__ __forceinline__ void cpasync16(uint32_t dst, const void* src) {
    asm volatile("cp.async.cg.shared.global [%0], [%1], 16;" :: "r"(dst), "l"(src));
}
#define CP_COMMIT() asm volatile("cp.async.commit_group;")
#define CP_WAIT(N)  asm volatile("cp.async.wait_group %0;" :: "n"(N))

__device__ __forceinline__ void split_bf16(float v, uint16_t& h, uint16_t& l) {
    __nv_bfloat16 hb = __float2bfloat16(v);
    float r = v - __bfloat162float(hb);
    h = __bfloat16_as_ushort(hb);
    l = __bfloat16_as_ushort(__float2bfloat16(r));
}

// 128x32 bf16 tile -> swizzled smem (2 x 16B per thread)
__device__ __forceinline__ void load_tile128(uint32_t sdst, const __nv_bfloat16* g,
                                             size_t ld, int t) {
    #pragma unroll
    for (int j = 0; j < 2; j++) {
        int i = t + j * NTH;
        int row = i >> 2, c = i & 3;
        cpasync16(sdst + SW64((row << 6) + (c << 4)), g + (size_t)row * ld + c * 8);
    }
}
__device__ __forceinline__ void load_chunk(uint32_t s,
                                           const __nv_bfloat16* Ah, const __nv_bfloat16* Al,
                                           const __nv_bfloat16* Bh, const __nv_bfloat16* Bl,
                                           size_t ldA, size_t ldB, int k0, int t) {
    load_tile128(s + SA_H, Ah + k0, ldA, t);
    load_tile128(s + SA_L, Al + k0, ldA, t);
    load_tile128(s + SB_H, Bh + k0, ldB, t);
    load_tile128(s + SB_L, Bl + k0, ldB, t);
}

// one BK=32 chunk: acc += Ah*Bh + Ah*Bl + Al*Bh  (warp tile 32x64, 4x2 grid)
__device__ __forceinline__ void compute_stage(uint32_t s, int wr, int wc, int lane,
                                              float acc[2][8][4]) {
    #pragma unroll
    for (int ks = 0; ks < 2; ks++) {
        const int k0 = ks * 16;
        uint32_t ah[2][4], al[2][4];
        const int arow = wr * 32 + (lane & 15);
        const int acol = k0 + ((lane >> 4) << 3);
        #pragma unroll
        for (int mi = 0; mi < 2; mi++) {
            uint32_t off = SW64(((arow + mi * 16) << 6) + (acol << 1));
            ldmx4(ah[mi], s + SA_H + off);
            ldmx4(al[mi], s + SA_L + off);
        }
        const int brow = wc * 64 + ((lane >> 4) << 3) + (lane & 7);
        const int bcol = k0 + (((lane >> 3) & 1) << 3);
        #pragma unroll
        for (int p = 0; p < 4; p++) {
            uint32_t bh[4], bl[4];
            uint32_t off = SW64(((brow + p * 16) << 6) + (bcol << 1));
            ldmx4(bh, s + SB_H + off);
            ldmx4(bl, s + SB_L + off);
            #pragma unroll
            for (int mi = 0; mi < 2; mi++) {
                mma16816(acc[mi][2 * p],     ah[mi], bh[0], bh[1]);
                mma16816(acc[mi][2 * p + 1], ah[mi], bh[2], bh[3]);
                mma16816(acc[mi][2 * p],     ah[mi], bl[0], bl[1]);
                mma16816(acc[mi][2 * p + 1], ah[mi], bl[2], bl[3]);
                mma16816(acc[mi][2 * p],     al[mi], bh[0], bh[1]);
                mma16816(acc[mi][2 * p + 1], al[mi], bh[2], bh[3]);
            }
        }
    }
}

// 3-stage pipeline, one barrier per chunk, depth-2 prefetch
#define GEMM_PIPELINE(Ah, Al, Bh, Bl, ldA, ldB, nch)                              \
    do {                                                                          \
        load_chunk(sb, Ah, Al, Bh, Bl, ldA, ldB, 0, t);                           \
        CP_COMMIT();                                                              \
        if ((nch) > 1) load_chunk(sb + STAGE, Ah, Al, Bh, Bl, ldA, ldB, BK, t);   \
        CP_COMMIT();                                                              \
        for (int c = 0; c < (nch); c++) {                                         \
            CP_WAIT(1);                                                           \
            __syncthreads();                                                      \
            if (c + 2 < (nch))                                                    \
                load_chunk(sb + ((c + 2) % NSTAGE) * STAGE, Ah, Al, Bh, Bl,       \
                           ldA, ldB, (c + 2) * BK, t);                            \
            CP_COMMIT();                                                          \
            compute_stage(sb + (c % NSTAGE) * STAGE, wr, wc, lane, acc);          \
        }                                                                         \
    } while (0)

// ---------------------------------------------------------------- split kernel
__global__ __launch_bounds__(NTH)
void split_kernel(const float* __restrict__ src, __nv_bfloat16* __restrict__ h,
                  __nv_bfloat16* __restrict__ l, int n4) {
    int i = blockIdx.x * NTH + threadIdx.x;
    if (i >= n4) return;
    float4 v = reinterpret_cast<const float4*>(src)[i];
    uint16_t h0, h1, h2, h3, l0, l1, l2, l3;
    split_bf16(v.x, h0, l0); split_bf16(v.y, h1, l1);
    split_bf16(v.z, h2, l2); split_bf16(v.w, h3, l3);
    reinterpret_cast<uint2*>(h)[i] =
        make_uint2((uint32_t)h0 | ((uint32_t)h1 << 16), (uint32_t)h2 | ((uint32_t)h3 << 16));
    reinterpret_cast<uint2*>(l)[i] =
        make_uint2((uint32_t)l0 | ((uint32_t)l1 << 16), (uint32_t)l2 | ((uint32_t)l3 << 16));
}

// ---------------------------------------------------------------- kernel: QKV
__global__ __launch_bounds__(NTH, 2)
void qkv_kernel() {
    extern __shared__ __align__(128) char smem[];
    const uint32_t sb = smem_u32(smem);
    const int t = threadIdx.x, wid = t >> 5, lane = t & 31;
    const int wr = wid & 3, wc = wid >> 2;
    const int which = blockIdx.z;
    const int m0 = blockIdx.y * BM;      // global row (b*SEQ+s)
    const int n0 = blockIdx.x * BN;

    const __nv_bfloat16* Ah = g_xh + (size_t)m0 * DM;
    const __nv_bfloat16* Al = g_xl + (size_t)m0 * DM;
    const __nv_bfloat16* Bh = g_Wh + (size_t)which * DM * DM + (size_t)n0 * DM;
    const __nv_bfloat16* Bl = g_Wl + (size_t)which * DM * DM + (size_t)n0 * DM;

    float acc[2][8][4];
    #pragma unroll
    for (int a = 0; a < 2; a++)
        #pragma unroll
        for (int b = 0; b < 8; b++)
            #pragma unroll
            for (int r = 0; r < 4; r++) acc[a][b][r] = 0.0f;

    GEMM_PIPELINE(Ah, Al, Bh, Bl, DM, DM, DM / BK);

    if (which < 2) {
        __nv_bfloat16* Dh = (which == 0) ? g_Qh : g_Kh;
        __nv_bfloat16* Dl = (which == 0) ? g_Ql : g_Kl;
        const float sc = (which == 0) ? SOFTMAX_SCALE : 1.0f;
        #pragma unroll
        for (int mi = 0; mi < 2; mi++) {
            #pragma unroll
            for (int ni = 0; ni < 8; ni++) {
                int row = m0 + wr * 32 + mi * 16 + (lane >> 2);
                int col = n0 + wc * 64 + ni * 8 + ((lane & 3) << 1);
                uint16_t h0, h1, l0, l1;
                split_bf16(acc[mi][ni][0] * sc, h0, l0);
                split_bf16(acc[mi][ni][1] * sc, h1, l1);
                *reinterpret_cast<uint32_t*>(&Dh[(size_t)row * DM + col]) =
                    (uint32_t)h0 | ((uint32_t)h1 << 16);
                *reinterpret_cast<uint32_t*>(&Dl[(size_t)row * DM + col]) =
                    (uint32_t)l0 | ((uint32_t)l1 << 16);
                split_bf16(acc[mi][ni][2] * sc, h0, l0);
                split_bf16(acc[mi][ni][3] * sc, h1, l1);
                *reinterpret_cast<uint32_t*>(&Dh[(size_t)(row + 8) * DM + col]) =
                    (uint32_t)h0 | ((uint32_t)h1 << 16);
                *reinterpret_cast<uint32_t*>(&Dl[(size_t)(row + 8) * DM + col]) =
                    (uint32_t)l0 | ((uint32_t)l1 << 16);
            }
        }
    } else {
        // V: transpose through smem, write V^T hi/lo coalesced
        __syncthreads();
        #pragma unroll
        for (int mi = 0; mi < 2; mi++) {
            #pragma unroll
            for (int ni = 0; ni < 8; ni++) {
                #pragma unroll
                for (int r = 0; r < 4; r++) {
                    int srow = wr * 32 + mi * 16 + (lane >> 2) + ((r >> 1) << 3);
                    int dcol = wc * 64 + ni * 8 + ((lane & 3) << 1) + (r & 1);
                    uint16_t h, l;
                    split_bf16(acc[mi][ni][r], h, l);
                    *reinterpret_cast<uint16_t*>(smem + dcol * 256 + srow * 2) = h;
                    *reinterpret_cast<uint16_t*>(smem + 32768 + dcol * 256 + srow * 2) = l;
                }
            }
        }
        __syncthreads();
        const int b = m0 >> 12, s0 = m0 & (SEQ - 1);
        const int d = t >> 1, half = t & 1;
        const uint4* sh = reinterpret_cast<const uint4*>(smem + d * 256 + half * 128);
        const uint4* sl = reinterpret_cast<const uint4*>(smem + 32768 + d * 256 + half * 128);
        size_t o = ((size_t)b * DM + n0 + d) * SEQ + s0 + half * 64;
        uint4* dh = reinterpret_cast<uint4*>(g_Vth + o);
        uint4* dl = reinterpret_cast<uint4*>(g_Vtl + o);
        #pragma unroll
        for (int q = 0; q < 8; q++) { dh[q] = sh[q]; dl[q] = sl[q]; }
    }
}

// ---------------------------------------------------------------- kernel: scores
__global__ __launch_bounds__(NTH, 2)
void scores_kernel(float* __restrict__ att) {
    const int kt = blockIdx.x, qt = blockIdx.y;
    const int b = blockIdx.z;
    float* __restrict__ attb = att + (size_t)b * SEQ * SEQ;
    const int t = threadIdx.x;

    if (kt > qt) {
        // fully masked tile: write zeros (covers poisoned upper triangle)
        int row = qt * BM + (t >> 1);
        int col = kt * BN + (t & 1) * 64;
        float4 z = make_float4(0.f, 0.f, 0.f, 0.f);
        float4* dst = reinterpret_cast<float4*>(&attb[(size_t)row * SEQ + col]);
        #pragma unroll
        for (int i = 0; i < 16; i++) dst[i] = z;
        return;
    }

    extern __shared__ __align__(128) char smem[];
    const uint32_t sb = smem_u32(smem);
    const int wid = t >> 5, lane = t & 31;
    const int wr = wid & 3, wc = wid >> 2;

    const size_t qr = ((size_t)b * SEQ + qt * BM) * DM;
    const size_t kr = ((size_t)b * SEQ + kt * BN) * DM;
    const __nv_bfloat16* Ah = g_Qh + qr;
    const __nv_bfloat16* Al = g_Ql + qr;
    const __nv_bfloat16* Bh = g_Kh + kr;
    const __nv_bfloat16* Bl = g_Kl + kr;

    float acc[2][8][4];
    #pragma unroll
    for (int a = 0; a < 2; a++)
        #pragma unroll
        for (int c = 0; c < 8; c++)
            #pragma unroll
            for (int r = 0; r < 4; r++) acc[a][c][r] = 0.0f;

    GEMM_PIPELINE(Ah, Al, Bh, Bl, DM, DM, DM / BK);

    #pragma unroll
    for (int mi = 0; mi < 2; mi++) {
        #pragma unroll
        for (int ni = 0; ni < 8; ni++) {
            int row = qt * BM + wr * 32 + mi * 16 + (lane >> 2);
            int col = kt * BN + wc * 64 + ni * 8 + ((lane & 3) << 1);
            *reinterpret_cast<float2*>(&attb[(size_t)row * SEQ + col]) =
                make_float2(acc[mi][ni][0], acc[mi][ni][1]);
            *reinterpret_cast<float2*>(&attb[(size_t)(row + 8) * SEQ + col]) =
                make_float2(acc[mi][ni][2], acc[mi][ni][3]);
        }
    }
}

// ---------------------------------------------------------------- kernel: softmax
__global__ __launch_bounds__(NTH)
void softmax_kernel(float* __restrict__ att) {
    const int rr = blockIdx.x;
    const int b = rr >> 12;
    const int q = rr & (SEQ - 1);
    float* __restrict__ row = att + (size_t)b * SEQ * SEQ + (size_t)q * SEQ;
    __nv_bfloat16* __restrict__ ph = g_Ph + (size_t)b * SEQ * SEQ + (size_t)q * SEQ;
    __nv_bfloat16* __restrict__ pl = g_Pl + (size_t)b * SEQ * SEQ + (size_t)q * SEQ;
    const int L = q + 1;
    const int jmax = ((q >> 7) + 1) << 7;   // pad to 128 for the AV gemm

    __shared__ float sm[SEQ];
    __shared__ float red[NTH];
    const int t = threadIdx.x;

    float mx = -INFINITY;
    for (int j = t; j < L; j += NTH) {
        float v = row[j];
        sm[j] = v;
        mx = fmaxf(mx, v);
    }
    red[t] = mx;
    __syncthreads();
    #pragma unroll
    for (int s = NTH / 2; s > 0; s >>= 1) {
        if (t < s) red[t] = fmaxf(red[t], red[t + s]);
        __syncthreads();
    }
    const float rowmax = red[0];
    __syncthreads();

    float sum = 0.0f;
    for (int j = t; j < L; j += NTH) {
        float e = __expf(sm[j] - rowmax);
        sm[j] = e;
        sum += e;
    }
    red[t] = sum;
    __syncthreads();
    #pragma unroll
    for (int s = NTH / 2; s > 0; s >>= 1) {
        if (t < s) red[t] += red[t + s];
        __syncthreads();
    }
    const float inv = 1.0f / red[0];

    // only the causal band (+pad to tile); tiles beyond jmax were zeroed by scores
    for (int j = t; j < jmax; j += NTH) {
        float v = (j < L) ? sm[j] * inv : 0.0f;
        row[j] = v;
        uint16_t h, l;
        split_bf16(v, h, l);
        ph[j] = __ushort_as_bfloat16(h);
        pl[j] = __ushort_as_bfloat16(l);
    }
}

// ---------------------------------------------------------------- kernel: AV + residual
__global__ __launch_bounds__(NTH, 2)
void av_kernel(const float* __restrict__ x, float* __restrict__ out) {
    const int b = blockIdx.z;
    const int qt = blockIdx.y;
    const int n0 = blockIdx.x * BN;
    const int m0 = qt * BM;              // batch-local q row

    extern __shared__ __align__(128) char smem[];
    const uint32_t sb = smem_u32(smem);
    const int t = threadIdx.x, wid = t >> 5, lane = t & 31;
    const int wr = wid & 3, wc = wid >> 2;

    const size_t pr = ((size_t)b * SEQ + m0) * SEQ;
    const size_t vr = ((size_t)b * DM + n0) * SEQ;
    const __nv_bfloat16* Ah = g_Ph + pr;
    const __nv_bfloat16* Al = g_Pl + pr;
    const __nv_bfloat16* Bh = g_Vth + vr;
    const __nv_bfloat16* Bl = g_Vtl + vr;

    float acc[2][8][4];
    #pragma unroll
    for (int a = 0; a < 2; a++)
        #pragma unroll
        for (int c = 0; c < 8; c++)
            #pragma unroll
            for (int r = 0; r < 4; r++) acc[a][c][r] = 0.0f;

    const int nch = ((qt + 1) * BM) / BK;   // causal truncation

    GEMM_PIPELINE(Ah, Al, Bh, Bl, SEQ, SEQ, nch);

    #pragma unroll
    for (int mi = 0; mi < 2; mi++) {
        #pragma unroll
        for (int ni = 0; ni < 8; ni++) {
            int row = m0 + wr * 32 + mi * 16 + (lane >> 2);
            int col = n0 + wc * 64 + ni * 8 + ((lane & 3) << 1);
            size_t base = ((size_t)b * SEQ + row) * DM + col;
            float2 xv = *reinterpret_cast<const float2*>(&x[base]);
            *reinterpret_cast<float2*>(&out[base]) =
                make_float2(acc[mi][ni][0] + xv.x, acc[mi][ni][1] + xv.y);
            size_t base8 = base + (size_t)8 * DM;
            float2 xv8 = *reinterpret_cast<const float2*>(&x[base8]);
            *reinterpret_cast<float2*>(&out[base8]) =
                make_float2(acc[mi][ni][2] + xv8.x, acc[mi][ni][3] + xv8.y);
        }
    }
}

// ---------------------------------------------------------------- launch
extern "C" void kernel_launch(void* const* d_in, const int* in_sizes, int n_in,
                              void* d_out, int out_size) {
    const float* x  = (const float*)d_in[0];
    const float* WQ = (const float*)d_in[1];
    const float* WK = (const float*)d_in[2];
    const float* WV = (const float*)d_in[3];

    float* out = (float*)d_out;                   // [B,S,D]
    float* att = out + (size_t)BSZ * SEQ * DM;    // [B,S,S]

    cudaFuncSetAttribute(qkv_kernel,    cudaFuncAttributeMaxDynamicSharedMemorySize, SMEM_TOTAL);
    cudaFuncSetAttribute(scores_kernel, cudaFuncAttributeMaxDynamicSharedMemorySize, SMEM_TOTAL);
    cudaFuncSetAttribute(av_kernel,     cudaFuncAttributeMaxDynamicSharedMemorySize, SMEM_TOTAL);

    __nv_bfloat16 *xh, *xl, *Wh, *Wl;
    cudaGetSymbolAddress((void**)&xh, g_xh);
    cudaGetSymbolAddress((void**)&xl, g_xl);
    cudaGetSymbolAddress((void**)&Wh, g_Wh);
    cudaGetSymbolAddress((void**)&Wl, g_Wl);

    // 0) split fp32 inputs into bf16 hi/lo
    split_kernel<<<(NROWS * DM / 4 + NTH - 1) / NTH, NTH>>>(x, xh, xl, NROWS * DM / 4);
    split_kernel<<<(DM * DM / 4 + NTH - 1) / NTH, NTH>>>(WQ, Wh, Wl, DM * DM / 4);
    split_kernel<<<(DM * DM / 4 + NTH - 1) / NTH, NTH>>>(WK, Wh + DM * DM, Wl + DM * DM, DM * DM / 4);
    split_kernel<<<(DM * DM / 4 + NTH - 1) / NTH, NTH>>>(WV, Wh + 2 * DM * DM, Wl + 2 * DM * DM, DM * DM / 4);

    // 1) QKV projections (Q pre-scaled; V transposed)
    dim3 g1(DM / BN, NROWS / BM, 3);
    qkv_kernel<<<g1, NTH, SMEM_TOTAL>>>();

    // 2) causal scores (fp32) into attention region; masked tiles zero-filled
    dim3 g2(SEQ / BN, SEQ / BM, BSZ);
    scores_kernel<<<g2, NTH, SMEM_TOTAL>>>(att);

    // 3) softmax: fp32 probs to d_out, bf16 hi/lo probs to scratch
    softmax_kernel<<<NROWS, NTH>>>(att);

    // 4) O = P @ V + x
    dim3 g4(DM / BN, SEQ / BM, BSZ);
    av_kernel<<<g4, NTH, SMEM_TOTAL>>>(x, out);
}

// round 7
// speedup vs baseline: 1.1848x; 1.0537x over previous
#include <cuda_runtime.h>
#include <cuda_bf16.h>
#include <math.h>
#include <stdint.h>

// ---------------------------------------------------------------- dims
#define BSZ 4
#define SEQ 4096
#define DM  512
#define NROWS (BSZ * SEQ)                 // 16384
#define NTH 256
#define BM 128
#define BN 128
#define BK 32
#define SOFTMAX_SCALE 0.04419417382415922f

// smem stage layout (bf16 tiles, 64-byte rows, SW64 swizzle)
#define SA_H 0
#define SA_L 8192
#define SB_H 16384
#define SB_L 24576
#define STAGE 32768
#define NSTAGE 3
#define SMEM_TOTAL (NSTAGE * STAGE)       // 98304 bytes -> 2 CTAs/SM

#define SW64(o) ((uint32_t)(o) ^ ((((uint32_t)(o)) >> 3) & 0x30u))

// ---------------------------------------------------------------- scratch
__device__ __nv_bfloat16 g_xh[(size_t)NROWS * DM];
__device__ __nv_bfloat16 g_xl[(size_t)NROWS * DM];
__device__ __nv_bfloat16 g_WqTh[DM * DM];   // Wq^T  [d][f]
__device__ __nv_bfloat16 g_WqTl[DM * DM];
__device__ __nv_bfloat16 g_WkTh[DM * DM];   // Wk^T  [e][f]
__device__ __nv_bfloat16 g_WkTl[DM * DM];
__device__ __nv_bfloat16 g_Wvh[DM * DM];    // Wv    [e][d]
__device__ __nv_bfloat16 g_Wvl[DM * DM];
__device__ __nv_bfloat16 g_MTh[DM * DM];    // (Wq^T Wk)^T * scale  [e][d]
__device__ __nv_bfloat16 g_MTl[DM * DM];
__device__ __nv_bfloat16 g_Gh[(size_t)NROWS * DM];   // G = x*M*scale
__device__ __nv_bfloat16 g_Gl[(size_t)NROWS * DM];
__device__ __nv_bfloat16 g_Vth[(size_t)BSZ * DM * SEQ];  // V^T [b][d][s]
__device__ __nv_bfloat16 g_Vtl[(size_t)BSZ * DM * SEQ];
__device__ __nv_bfloat16 g_Ph[(size_t)BSZ * SEQ * SEQ];  // probs hi/lo
__device__ __nv_bfloat16 g_Pl[(size_t)BSZ * SEQ * SEQ];

// ---------------------------------------------------------------- helpers
__device__ __forceinline__ uint32_t smem_u32(const void* p) {
    return (uint32_t)__cvta_generic_to_shared(p);
}
__device__ __forceinline__ void ldmx4(uint32_t r[4], uint32_t addr) {
    asm volatile("ldmatrix.sync.aligned.m8n8.x4.shared.b16 {%0,%1,%2,%3}, [%4];"
                 : "=r"(r[0]), "=r"(r[1]), "=r"(r[2]), "=r"(r[3]) : "r"(addr));
}
__device__ __forceinline__ void mma16816(float d[4], const uint32_t a[4],
                                         uint32_t b0, uint32_t b1) {
    asm volatile("mma.sync.aligned.m16n8k16.row.col.f32.bf16.bf16.f32 "
                 "{%0,%1,%2,%3}, {%4,%5,%6,%7}, {%8,%9}, {%0,%1,%2,%3};"
                 : "+f"(d[0]), "+f"(d[1]), "+f"(d[2]), "+f"(d[3])
                 : "r"(a[0]), "r"(a[1]), "r"(a[2]), "r"(a[3]), "r"(b0), "r"(b1));
}
__device__ __forceinline__ void cpasync16(uint32_t dst, const void* src) {
    asm volatile("cp.async.cg.shared.global [%0], [%1], 16;" :: "r"(dst), "l"(src));
}
#define CP_COMMIT() asm volatile("cp.async.commit_group;")
#define CP_WAIT(N)  asm volatile("cp.async.wait_group %0;" :: "n"(N))

__device__ __forceinline__ void split_bf16(float v, uint16_t& h, uint16_t& l) {
    __nv_bfloat16 hb = __float2bfloat16(v);
    float r = v - __bfloat162float(hb);
    h = __bfloat16_as_ushort(hb);
    l = __bfloat16_as_ushort(__float2bfloat16(r));
}

// 128x32 bf16 tile -> swizzled smem (2 x 16B per thread)
__device__ __forceinline__ void load_tile128(uint32_t sdst, const __nv_bfloat16* g,
                                             size_t ld, int t) {
    #pragma unroll
    for (int j = 0; j < 2; j++) {
        int i = t + j * NTH;
        int row = i >> 2, c = i & 3;
        cpasync16(sdst + SW64((row << 6) + (c << 4)), g + (size_t)row * ld + c * 8);
    }
}
__device__ __forceinline__ void load_chunk(uint32_t s,
                                           const __nv_bfloat16* Ah, const __nv_bfloat16* Al,
                                           const __nv_bfloat16* Bh, const __nv_bfloat16* Bl,
                                           size_t ldA, size_t ldB, int k0, int t) {
    load_tile128(s + SA_H, Ah + k0, ldA, t);
    load_tile128(s + SA_L, Al + k0, ldA, t);
    load_tile128(s + SB_H, Bh + k0, ldB, t);
    load_tile128(s + SB_L, Bl + k0, ldB, t);
}

// one BK=32 chunk: acc += Ah*Bh + Ah*Bl + Al*Bh  (warp tile 32x64, 4x2 grid)
__device__ __forceinline__ void compute_stage(uint32_t s, int wr, int wc, int lane,
                                              float acc[2][8][4]) {
    #pragma unroll
    for (int ks = 0; ks < 2; ks++) {
        const int k0 = ks * 16;
        uint32_t ah[2][4], al[2][4];
        const int arow = wr * 32 + (lane & 15);
        const int acol = k0 + ((lane >> 4) << 3);
        #pragma unroll
        for (int mi = 0; mi < 2; mi++) {
            uint32_t off = SW64(((arow + mi * 16) << 6) + (acol << 1));
            ldmx4(ah[mi], s + SA_H + off);
            ldmx4(al[mi], s + SA_L + off);
        }
        const int brow = wc * 64 + ((lane >> 4) << 3) + (lane & 7);
        const int bcol = k0 + (((lane >> 3) & 1) << 3);
        #pragma unroll
        for (int p = 0; p < 4; p++) {
            uint32_t bh[4], bl[4];
            uint32_t off = SW64(((brow + p * 16) << 6) + (bcol << 1));
            ldmx4(bh, s + SB_H + off);
            ldmx4(bl, s + SB_L + off);
            #pragma unroll
            for (int mi = 0; mi < 2; mi++) {
                mma16816(acc[mi][2 * p],     ah[mi], bh[0], bh[1]);
                mma16816(acc[mi][2 * p + 1], ah[mi], bh[2], bh[3]);
                mma16816(acc[mi][2 * p],     ah[mi], bl[0], bl[1]);
                mma16816(acc[mi][2 * p + 1], ah[mi], bl[2], bl[3]);
                mma16816(acc[mi][2 * p],     al[mi], bh[0], bh[1]);
                mma16816(acc[mi][2 * p + 1], al[mi], bh[2], bh[3]);
            }
        }
    }
}

// 3-stage pipeline, one barrier per chunk, depth-2 prefetch
#define GEMM_PIPELINE(Ah, Al, Bh, Bl, ldA, ldB, nch)                              \
    do {                                                                          \
        load_chunk(sb, Ah, Al, Bh, Bl, ldA, ldB, 0, t);                           \
        CP_COMMIT();                                                              \
        if ((nch) > 1) load_chunk(sb + STAGE, Ah, Al, Bh, Bl, ldA, ldB, BK, t);   \
        CP_COMMIT();                                                              \
        for (int c = 0; c < (nch); c++) {                                         \
            CP_WAIT(1);                                                           \
            __syncthreads();                                                      \
            if (c + 2 < (nch))                                                    \
                load_chunk(sb + ((c + 2) % NSTAGE) * STAGE, Ah, Al, Bh, Bl,       \
                           ldA, ldB, (c + 2) * BK, t);                            \
            CP_COMMIT();                                                          \
            compute_stage(sb + (c % NSTAGE) * STAGE, wr, wc, lane, acc);          \
        }                                                                         \
    } while (0)

// ---------------------------------------------------------------- split kernel
__global__ __launch_bounds__(NTH)
void split_kernel(const float* __restrict__ src, __nv_bfloat16* __restrict__ h,
                  __nv_bfloat16* __restrict__ l, int n4) {
    int i = blockIdx.x * NTH + threadIdx.x;
    if (i >= n4) return;
    float4 v = reinterpret_cast<const float4*>(src)[i];
    uint16_t h0, h1, h2, h3, l0, l1, l2, l3;
    split_bf16(v.x, h0, l0); split_bf16(v.y, h1, l1);
    split_bf16(v.z, h2, l2); split_bf16(v.w, h3, l3);
    reinterpret_cast<uint2*>(h)[i] =
        make_uint2((uint32_t)h0 | ((uint32_t)h1 << 16), (uint32_t)h2 | ((uint32_t)h3 << 16));
    reinterpret_cast<uint2*>(l)[i] =
        make_uint2((uint32_t)l0 | ((uint32_t)l1 << 16), (uint32_t)l2 | ((uint32_t)l3 << 16));
}

// transpose + split: out[i][j] = in[j][i], 512x512
__global__ __launch_bounds__(NTH)
void tsplit_kernel(const float* __restrict__ src, __nv_bfloat16* __restrict__ th,
                   __nv_bfloat16* __restrict__ tl) {
    __shared__ float tile[32][33];
    const int bx = blockIdx.x * 32, by = blockIdx.y * 32;
    const int tx = threadIdx.x & 31, ty = threadIdx.x >> 5;   // 8 rows of 32
    #pragma unroll
    for (int r = ty; r < 32; r += 8)
        tile[r][tx] = src[(size_t)(by + r) * DM + bx + tx];
    __syncthreads();
    #pragma unroll
    for (int r = ty; r < 32; r += 8) {
        float v = tile[tx][r];
        uint16_t h, l;
        split_bf16(v, h, l);
        th[(size_t)(bx + r) * DM + by + tx] = __ushort_as_bfloat16(h);
        tl[(size_t)(bx + r) * DM + by + tx] = __ushort_as_bfloat16(l);
    }
}

// ---------------------------------------------------------------- kernel: M^T = Wk^T * Wq (scaled)
__global__ __launch_bounds__(NTH, 2)
void mgemm_kernel() {
    extern __shared__ __align__(128) char smem[];
    const uint32_t sb = smem_u32(smem);
    const int t = threadIdx.x, wid = t >> 5, lane = t & 31;
    const int wr = wid & 3, wc = wid >> 2;
    const int m0 = blockIdx.y * BM;
    const int n0 = blockIdx.x * BN;

    const __nv_bfloat16* Ah = g_WkTh + (size_t)m0 * DM;
    const __nv_bfloat16* Al = g_WkTl + (size_t)m0 * DM;
    const __nv_bfloat16* Bh = g_WqTh + (size_t)n0 * DM;
    const __nv_bfloat16* Bl = g_WqTl + (size_t)n0 * DM;

    float acc[2][8][4];
    #pragma unroll
    for (int a = 0; a < 2; a++)
        #pragma unroll
        for (int b = 0; b < 8; b++)
            #pragma unroll
            for (int r = 0; r < 4; r++) acc[a][b][r] = 0.0f;

    GEMM_PIPELINE(Ah, Al, Bh, Bl, DM, DM, DM / BK);

    // C[e,d] = scale * sum_f Wk[f,e] Wq[f,d]  -> MT split
    #pragma unroll
    for (int mi = 0; mi < 2; mi++) {
        #pragma unroll
        for (int ni = 0; ni < 8; ni++) {
            int row = m0 + wr * 32 + mi * 16 + (lane >> 2);
            int col = n0 + wc * 64 + ni * 8 + ((lane & 3) << 1);
            uint16_t h0, h1, l0, l1;
            split_bf16(acc[mi][ni][0] * SOFTMAX_SCALE, h0, l0);
            split_bf16(acc[mi][ni][1] * SOFTMAX_SCALE, h1, l1);
            *reinterpret_cast<uint32_t*>(&g_MTh[(size_t)row * DM + col]) =
                (uint32_t)h0 | ((uint32_t)h1 << 16);
            *reinterpret_cast<uint32_t*>(&g_MTl[(size_t)row * DM + col]) =
                (uint32_t)l0 | ((uint32_t)l1 << 16);
            split_bf16(acc[mi][ni][2] * SOFTMAX_SCALE, h0, l0);
            split_bf16(acc[mi][ni][3] * SOFTMAX_SCALE, h1, l1);
            *reinterpret_cast<uint32_t*>(&g_MTh[(size_t)(row + 8) * DM + col]) =
                (uint32_t)h0 | ((uint32_t)h1 << 16);
            *reinterpret_cast<uint32_t*>(&g_MTl[(size_t)(row + 8) * DM + col]) =
                (uint32_t)l0 | ((uint32_t)l1 << 16);
        }
    }
}

// ---------------------------------------------------------------- kernel: proj (G and V)
// z=0: G = x * MT^T (scale folded into MT), split write
// z=1: V = x * Wv^T, transposed split write
__global__ __launch_bounds__(NTH, 2)
void proj_kernel() {
    extern __shared__ __align__(128) char smem[];
    const uint32_t sb = smem_u32(smem);
    const int t = threadIdx.x, wid = t >> 5, lane = t & 31;
    const int wr = wid & 3, wc = wid >> 2;
    const int which = blockIdx.z;
    const int m0 = blockIdx.y * BM;      // global row (b*SEQ+s)
    const int n0 = blockIdx.x * BN;

    const __nv_bfloat16* Ah = g_xh + (size_t)m0 * DM;
    const __nv_bfloat16* Al = g_xl + (size_t)m0 * DM;
    const __nv_bfloat16* Bh = (which == 0 ? g_MTh : g_Wvh) + (size_t)n0 * DM;
    const __nv_bfloat16* Bl = (which == 0 ? g_MTl : g_Wvl) + (size_t)n0 * DM;

    float acc[2][8][4];
    #pragma unroll
    for (int a = 0; a < 2; a++)
        #pragma unroll
        for (int b = 0; b < 8; b++)
            #pragma unroll
            for (int r = 0; r < 4; r++) acc[a][b][r] = 0.0f;

    GEMM_PIPELINE(Ah, Al, Bh, Bl, DM, DM, DM / BK);

    if (which == 0) {
        #pragma unroll
        for (int mi = 0; mi < 2; mi++) {
            #pragma unroll
            for (int ni = 0; ni < 8; ni++) {
                int row = m0 + wr * 32 + mi * 16 + (lane >> 2);
                int col = n0 + wc * 64 + ni * 8 + ((lane & 3) << 1);
                uint16_t h0, h1, l0, l1;
                split_bf16(acc[mi][ni][0], h0, l0);
                split_bf16(acc[mi][ni][1], h1, l1);
                *reinterpret_cast<uint32_t*>(&g_Gh[(size_t)row * DM + col]) =
                    (uint32_t)h0 | ((uint32_t)h1 << 16);
                *reinterpret_cast<uint32_t*>(&g_Gl[(size_t)row * DM + col]) =
                    (uint32_t)l0 | ((uint32_t)l1 << 16);
                split_bf16(acc[mi][ni][2], h0, l0);
                split_bf16(acc[mi][ni][3], h1, l1);
                *reinterpret_cast<uint32_t*>(&g_Gh[(size_t)(row + 8) * DM + col]) =
                    (uint32_t)h0 | ((uint32_t)h1 << 16);
                *reinterpret_cast<uint32_t*>(&g_Gl[(size_t)(row + 8) * DM + col]) =
                    (uint32_t)l0 | ((uint32_t)l1 << 16);
            }
        }
    } else {
        // V: transpose through smem, write V^T hi/lo coalesced
        __syncthreads();
        #pragma unroll
        for (int mi = 0; mi < 2; mi++) {
            #pragma unroll
            for (int ni = 0; ni < 8; ni++) {
                #pragma unroll
                for (int r = 0; r < 4; r++) {
                    int srow = wr * 32 + mi * 16 + (lane >> 2) + ((r >> 1) << 3);
                    int dcol = wc * 64 + ni * 8 + ((lane & 3) << 1) + (r & 1);
                    uint16_t h, l;
                    split_bf16(acc[mi][ni][r], h, l);
                    *reinterpret_cast<uint16_t*>(smem + dcol * 256 + srow * 2) = h;
                    *reinterpret_cast<uint16_t*>(smem + 32768 + dcol * 256 + srow * 2) = l;
                }
            }
        }
        __syncthreads();
        const int b = m0 >> 12, s0 = m0 & (SEQ - 1);
        const int d = t >> 1, half = t & 1;
        const uint4* sh = reinterpret_cast<const uint4*>(smem + d * 256 + half * 128);
        const uint4* sl = reinterpret_cast<const uint4*>(smem + 32768 + d * 256 + half * 128);
        size_t o = ((size_t)b * DM + n0 + d) * SEQ + s0 + half * 64;
        uint4* dh = reinterpret_cast<uint4*>(g_Vth + o);
        uint4* dl = reinterpret_cast<uint4*>(g_Vtl + o);
        #pragma unroll
        for (int q = 0; q < 8; q++) { dh[q] = sh[q]; dl[q] = sl[q]; }
    }
}

// ---------------------------------------------------------------- kernel: scores  S = G x^T
__global__ __launch_bounds__(NTH, 2)
void scores_kernel(float* __restrict__ att) {
    const int kt = blockIdx.x, qt = blockIdx.y;
    const int b = blockIdx.z;
    float* __restrict__ attb = att + (size_t)b * SEQ * SEQ;
    const int t = threadIdx.x;

    if (kt > qt) {
        // fully masked tile: write zeros (covers poisoned upper triangle)
        int row = qt * BM + (t >> 1);
        int col = kt * BN + (t & 1) * 64;
        float4 z = make_float4(0.f, 0.f, 0.f, 0.f);
        float4* dst = reinterpret_cast<float4*>(&attb[(size_t)row * SEQ + col]);
        #pragma unroll
        for (int i = 0; i < 16; i++) dst[i] = z;
        return;
    }

    extern __shared__ __align__(128) char smem[];
    const uint32_t sb = smem_u32(smem);
    const int wid = t >> 5, lane = t & 31;
    const int wr = wid & 3, wc = wid >> 2;

    const size_t qr = ((size_t)b * SEQ + qt * BM) * DM;
    const size_t kr = ((size_t)b * SEQ + kt * BN) * DM;
    const __nv_bfloat16* Ah = g_Gh + qr;
    const __nv_bfloat16* Al = g_Gl + qr;
    const __nv_bfloat16* Bh = g_xh + kr;
    const __nv_bfloat16* Bl = g_xl + kr;

    float acc[2][8][4];
    #pragma unroll
    for (int a = 0; a < 2; a++)
        #pragma unroll
        for (int c = 0; c < 8; c++)
            #pragma unroll
            for (int r = 0; r < 4; r++) acc[a][c][r] = 0.0f;

    GEMM_PIPELINE(Ah, Al, Bh, Bl, DM, DM, DM / BK);

    #pragma unroll
    for (int mi = 0; mi < 2; mi++) {
        #pragma unroll
        for (int ni = 0; ni < 8; ni++) {
            int row = qt * BM + wr * 32 + mi * 16 + (lane >> 2);
            int col = kt * BN + wc * 64 + ni * 8 + ((lane & 3) << 1);
            *reinterpret_cast<float2*>(&attb[(size_t)row * SEQ + col]) =
                make_float2(acc[mi][ni][0], acc[mi][ni][1]);
            *reinterpret_cast<float2*>(&attb[(size_t)(row + 8) * SEQ + col]) =
                make_float2(acc[mi][ni][2], acc[mi][ni][3]);
        }
    }
}

// ---------------------------------------------------------------- kernel: softmax (vectorized)
__global__ __launch_bounds__(NTH)
void softmax_kernel(float* __restrict__ att) {
    const int rr = blockIdx.x;
    const int b = rr >> 12;
    const int q = rr & (SEQ - 1);
    float* __restrict__ row = att + (size_t)b * SEQ * SEQ + (size_t)q * SEQ;
    __nv_bfloat16* __restrict__ ph = g_Ph + (size_t)b * SEQ * SEQ + (size_t)q * SEQ;
    __nv_bfloat16* __restrict__ pl = g_Pl + (size_t)b * SEQ * SEQ + (size_t)q * SEQ;
    const int L = q + 1;
    const int L4 = (L + 3) >> 2;
    const int jmax4 = (((q >> 7) + 1) << 7) >> 2;   // pad to 128-tile, /4

    __shared__ float4 sm4[SEQ / 4];
    __shared__ float red[NTH];
    const int t = threadIdx.x;

    float mx = -INFINITY;
    for (int j4 = t; j4 < L4; j4 += NTH) {
        float4 v = reinterpret_cast<const float4*>(row)[j4];
        int base = j4 << 2;
        float m1 = (base + 1 < L) ? v.y : -INFINITY;
        float m2 = (base + 2 < L) ? v.z : -INFINITY;
        float m3 = (base + 3 < L) ? v.w : -INFINITY;
        mx = fmaxf(mx, fmaxf(fmaxf(v.x, m1), fmaxf(m2, m3)));
        sm4[j4] = v;
    }
    red[t] = mx;
    __syncthreads();
    #pragma unroll
    for (int s = NTH / 2; s > 0; s >>= 1) {
        if (t < s) red[t] = fmaxf(red[t], red[t + s]);
        __syncthreads();
    }
    const float rowmax = red[0];
    __syncthreads();

    float sum = 0.0f;
    for (int j4 = t; j4 < L4; j4 += NTH) {
        float4 v = sm4[j4];
        int base = j4 << 2;
        float e0 = __expf(v.x - rowmax);
        float e1 = (base + 1 < L) ? __expf(v.y - rowmax) : 0.0f;
        float e2 = (base + 2 < L) ? __expf(v.z - rowmax) : 0.0f;
        float e3 = (base + 3 < L) ? __expf(v.w - rowmax) : 0.0f;
        sm4[j4] = make_float4(e0, e1, e2, e3);
        sum += (e0 + e1) + (e2 + e3);
    }
    red[t] = sum;
    __syncthreads();
    #pragma unroll
    for (int s = NTH / 2; s > 0; s >>= 1) {
        if (t < s) red[t] += red[t + s];
        __syncthreads();
    }
    const float inv = 1.0f / red[0];

    for (int j4 = t; j4 < jmax4; j4 += NTH) {
        float4 v = (j4 < L4) ? sm4[j4] : make_float4(0.f, 0.f, 0.f, 0.f);
        float4 o = make_float4(v.x * inv, v.y * inv, v.z * inv, v.w * inv);
        reinterpret_cast<float4*>(row)[j4] = o;
        uint16_t h0, h1, h2, h3, l0, l1, l2, l3;
        split_bf16(o.x, h0, l0); split_bf16(o.y, h1, l1);
        split_bf16(o.z, h2, l2); split_bf16(o.w, h3, l3);
        reinterpret_cast<uint2*>(ph)[j4] =
            make_uint2((uint32_t)h0 | ((uint32_t)h1 << 16), (uint32_t)h2 | ((uint32_t)h3 << 16));
        reinterpret_cast<uint2*>(pl)[j4] =
            make_uint2((uint32_t)l0 | ((uint32_t)l1 << 16), (uint32_t)l2 | ((uint32_t)l3 << 16));
    }
}

// ---------------------------------------------------------------- kernel: AV + residual
__global__ __launch_bounds__(NTH, 2)
void av_kernel(const float* __restrict__ x, float* __restrict__ out) {
    const int b = blockIdx.z;
    const int qt = blockIdx.y;
    const int n0 = blockIdx.x * BN;
    const int m0 = qt * BM;              // batch-local q row

    extern __shared__ __align__(128) char smem[];
    const uint32_t sb = smem_u32(smem);
    const int t = threadIdx.x, wid = t >> 5, lane = t & 31;
    const int wr = wid & 3, wc = wid >> 2;

    const size_t pr = ((size_t)b * SEQ + m0) * SEQ;
    const size_t vr = ((size_t)b * DM + n0) * SEQ;
    const __nv_bfloat16* Ah = g_Ph + pr;
    const __nv_bfloat16* Al = g_Pl + pr;
    const __nv_bfloat16* Bh = g_Vth + vr;
    const __nv_bfloat16* Bl = g_Vtl + vr;

    float acc[2][8][4];
    #pragma unroll
    for (int a = 0; a < 2; a++)
        #pragma unroll
        for (int c = 0; c < 8; c++)
            #pragma unroll
            for (int r = 0; r < 4; r++) acc[a][c][r] = 0.0f;

    const int nch = ((qt + 1) * BM) / BK;   // causal truncation

    GEMM_PIPELINE(Ah, Al, Bh, Bl, SEQ, SEQ, nch);

    #pragma unroll
    for (int mi = 0; mi < 2; mi++) {
        #pragma unroll
        for (int ni = 0; ni < 8; ni++) {
            int row = m0 + wr * 32 + mi * 16 + (lane >> 2);
            int col = n0 + wc * 64 + ni * 8 + ((lane & 3) << 1);
            size_t base = ((size_t)b * SEQ + row) * DM + col;
            float2 xv = *reinterpret_cast<const float2*>(&x[base]);
            *reinterpret_cast<float2*>(&out[base]) =
                make_float2(acc[mi][ni][0] + xv.x, acc[mi][ni][1] + xv.y);
            size_t base8 = base + (size_t)8 * DM;
            float2 xv8 = *reinterpret_cast<const float2*>(&x[base8]);
            *reinterpret_cast<float2*>(&out[base8]) =
                make_float2(acc[mi][ni][2] + xv8.x, acc[mi][ni][3] + xv8.y);
        }
    }
}

// ---------------------------------------------------------------- launch
extern "C" void kernel_launch(void* const* d_in, const int* in_sizes, int n_in,
                              void* d_out, int out_size) {
    const float* x  = (const float*)d_in[0];
    const float* WQ = (const float*)d_in[1];
    const float* WK = (const float*)d_in[2];
    const float* WV = (const float*)d_in[3];

    float* out = (float*)d_out;                   // [B,S,D]
    float* att = out + (size_t)BSZ * SEQ * DM;    // [B,S,S]

    cudaFuncSetAttribute(mgemm_kernel,  cudaFuncAttributeMaxDynamicSharedMemorySize, SMEM_TOTAL);
    cudaFuncSetAttribute(proj_kernel,   cudaFuncAttributeMaxDynamicSharedMemorySize, SMEM_TOTAL);
    cudaFuncSetAttribute(scores_kernel, cudaFuncAttributeMaxDynamicSharedMemorySize, SMEM_TOTAL);
    cudaFuncSetAttribute(av_kernel,     cudaFuncAttributeMaxDynamicSharedMemorySize, SMEM_TOTAL);

    __nv_bfloat16 *xh, *xl, *wqth, *wqtl, *wkth, *wktl, *wvh, *wvl;
    cudaGetSymbolAddress((void**)&xh, g_xh);
    cudaGetSymbolAddress((void**)&xl, g_xl);
    cudaGetSymbolAddress((void**)&wqth, g_WqTh);
    cudaGetSymbolAddress((void**)&wqtl, g_WqTl);
    cudaGetSymbolAddress((void**)&wkth, g_WkTh);
    cudaGetSymbolAddress((void**)&wktl, g_WkTl);
    cudaGetSymbolAddress((void**)&wvh, g_Wvh);
    cudaGetSymbolAddress((void**)&wvl, g_Wvl);

    // 0) splits / transposed splits
    split_kernel<<<(NROWS * DM / 4 + NTH - 1) / NTH, NTH>>>(x, xh, xl, NROWS * DM / 4);
    split_kernel<<<(DM * DM / 4 + NTH - 1) / NTH, NTH>>>(WV, wvh, wvl, DM * DM / 4);
    dim3 gt(DM / 32, DM / 32);
    tsplit_kernel<<<gt, NTH>>>(WQ, wqth, wqtl);
    tsplit_kernel<<<gt, NTH>>>(WK, wkth, wktl);

    // 1) M^T = scale * Wk^T Wq  (512x512)
    dim3 gm(DM / BN, DM / BM);
    mgemm_kernel<<<gm, NTH, SMEM_TOTAL>>>();

    // 2) G = x M (scale folded), V = x Wv^T (transposed)
    dim3 g1(DM / BN, NROWS / BM, 2);
    proj_kernel<<<g1, NTH, SMEM_TOTAL>>>();

    // 3) causal scores S = G x^T; masked tiles zero-filled
    dim3 g2(SEQ / BN, SEQ / BM, BSZ);
    scores_kernel<<<g2, NTH, SMEM_TOTAL>>>(att);

    // 4) softmax: fp32 probs to d_out, bf16 hi/lo probs to scratch
    softmax_kernel<<<NROWS, NTH>>>(att);

    // 5) O = P @ V + x
    dim3 g4(DM / BN, SEQ / BM, BSZ);
    av_kernel<<<g4, NTH, SMEM_TOTAL>>>(x, out);
}

// round 9
// speedup vs baseline: 1.2654x; 1.0679x over previous
#include <cuda_runtime.h>
#include <cuda_bf16.h>
#include <math.h>
#include <stdint.h>

// ---------------------------------------------------------------- dims
#define BSZ 4
#define SEQ 4096
#define DM  512
#define NROWS (BSZ * SEQ)                 // 16384
#define NTH 256
#define BM 128
#define BN 128
#define BK 32
#define SOFTMAX_SCALE 0.04419417382415922f

// smem stage layout (bf16 tiles, 64-byte rows, SW64 swizzle)
// regions within a stage: AH 0, AL 8192, BH 16384, BL 24576
#define STAGE 32768
#define NSTAGE 3
#define SMEM_TOTAL (NSTAGE * STAGE)       // 98304 bytes -> 2 CTAs/SM

#define SW64(o) ((uint32_t)(o) ^ ((((uint32_t)(o)) >> 3) & 0x30u))

// ---------------------------------------------------------------- scratch
__device__ __nv_bfloat16 g_xh[(size_t)NROWS * DM];
__device__ __nv_bfloat16 g_xl[(size_t)NROWS * DM];
__device__ __nv_bfloat16 g_WqTh[DM * DM];   // Wq^T  [d][f]
__device__ __nv_bfloat16 g_WqTl[DM * DM];
__device__ __nv_bfloat16 g_WkTh[DM * DM];   // Wk^T  [e][f]
__device__ __nv_bfloat16 g_WkTl[DM * DM];
__device__ __nv_bfloat16 g_Wvh[DM * DM];    // Wv    [e][d]
__device__ __nv_bfloat16 g_Wvl[DM * DM];
__device__ __nv_bfloat16 g_MTh[DM * DM];    // (Wq^T Wk)^T * scale  [e][d]
__device__ __nv_bfloat16 g_MTl[DM * DM];
__device__ __nv_bfloat16 g_Gh[(size_t)NROWS * DM];   // G = x*M*scale
__device__ __nv_bfloat16 g_Gl[(size_t)NROWS * DM];
__device__ __nv_bfloat16 g_Vth[(size_t)BSZ * DM * SEQ];  // V^T [b][d][s]
__device__ __nv_bfloat16 g_Vtl[(size_t)BSZ * DM * SEQ];
__device__ __nv_bfloat16 g_Ph[(size_t)BSZ * SEQ * SEQ];  // probs hi/lo
__device__ __nv_bfloat16 g_Pl[(size_t)BSZ * SEQ * SEQ];

// ---------------------------------------------------------------- helpers
__device__ __forceinline__ uint32_t smem_u32(const void* p) {
    return (uint32_t)__cvta_generic_to_shared(p);
}
__device__ __forceinline__ void ldmx4(uint32_t r[4], uint32_t addr) {
    asm volatile("ldmatrix.sync.aligned.m8n8.x4.shared.b16 {%0,%1,%2,%3}, [%4];"
                 : "=r"(r[0]), "=r"(r[1]), "=r"(r[2]), "=r"(r[3]) : "r"(addr));
}
__device__ __forceinline__ void mma16816(float d[4], const uint32_t a[4],
                                         uint32_t b0, uint32_t b1) {
    asm volatile("mma.sync.aligned.m16n8k16.row.col.f32.bf16.bf16.f32 "
                 "{%0,%1,%2,%3}, {%4,%5,%6,%7}, {%8,%9}, {%0,%1,%2,%3};"
                 : "+f"(d[0]), "+f"(d[1]), "+f"(d[2]), "+f"(d[3])
                 : "r"(a[0]), "r"(a[1]), "r"(a[2]), "r"(a[3]), "r"(b0), "r"(b1));
}
__device__ __forceinline__ void cpasync16(uint32_t dst, const void* src) {
    asm volatile("cp.async.cg.shared.global [%0], [%1], 16;" :: "r"(dst), "l"(src));
}
#define CP_COMMIT() asm volatile("cp.async.commit_group;")
#define CP_WAIT(N)  asm volatile("cp.async.wait_group %0;" :: "n"(N))

__device__ __forceinline__ void split_bf16(float v, uint16_t& h, uint16_t& l) {
    __nv_bfloat16 hb = __float2bfloat16(v);
    float r = v - __bfloat162float(hb);
    h = __bfloat16_as_ushort(hb);
    l = __bfloat16_as_ushort(__float2bfloat16(r));
}

// ---------------------------------------------------------------- GEMM engine
// Strength-reduced pipeline: all smem addresses are (2 base offsets + imm).
// ks step uses XOR (swizzle-correct since base column bit5 is clear);
// row steps (+1024, +4096) and region offsets never touch swizzle keys.
// acc += Ah*Bh + Ah*Bl + Al*Bh over nch chunks of BK=32.
__device__ __forceinline__ void run_gemm(
    uint32_t sb, int t, int wr, int wc, int lane,
    const __nv_bfloat16* Ah, const __nv_bfloat16* Al,
    const __nv_bfloat16* Bh, const __nv_bfloat16* Bl,
    size_t ldA, size_t ldB, int nch, float acc[2][8][4])
{
    // per-thread cp.async mapping: row = t>>2 (0..63), elem col = (t&3)*8;
    // second vector at row+64 -> smem offset +4096 (swizzle-invariant).
    const int lrow = t >> 2;
    const int lc8 = (t & 3) << 3;
    const uint32_t sdst = SW64((lrow << 6) + (lc8 << 1));
    const __nv_bfloat16* pAh = Ah + (size_t)lrow * ldA + lc8;
    const __nv_bfloat16* pAl = Al + (size_t)lrow * ldA + lc8;
    const __nv_bfloat16* pBh = Bh + (size_t)lrow * ldB + lc8;
    const __nv_bfloat16* pBl = Bl + (size_t)lrow * ldB + lc8;
    const size_t a64 = (size_t)64 * ldA;
    const size_t b64 = (size_t)64 * ldB;

    // ldmatrix base offsets (raw column byte has bit5 clear -> ks via XOR 32)
    const uint32_t aoff = SW64(((wr * 32 + (lane & 15)) << 6) + (((lane >> 4) << 3) << 1));
    const uint32_t boff = SW64(((wc * 64 + ((lane >> 4) << 3) + (lane & 7)) << 6)
                               + ((((lane >> 3) & 1) << 3) << 1));

    uint32_t s0 = sb, s1 = sb + STAGE, s2 = sb + 2 * STAGE;

#define LOADC(d)                                                                  \
    do {                                                                          \
        cpasync16((d) + sdst,                 pAh);                               \
        cpasync16((d) + sdst + 4096,          pAh + a64);                         \
        cpasync16((d) + 8192 + sdst,          pAl);                               \
        cpasync16((d) + 8192 + sdst + 4096,   pAl + a64);                         \
        cpasync16((d) + 16384 + sdst,         pBh);                               \
        cpasync16((d) + 16384 + sdst + 4096,  pBh + b64);                         \
        cpasync16((d) + 24576 + sdst,         pBl);                               \
        cpasync16((d) + 24576 + sdst + 4096,  pBl + b64);                         \
        pAh += BK; pAl += BK; pBh += BK; pBl += BK;                               \
    } while (0)

    LOADC(s0);
    CP_COMMIT();
    if (nch > 1) LOADC(s1);
    CP_COMMIT();

    for (int c = 0; c < nch; c++) {
        CP_WAIT(1);
        __syncthreads();
        if (c + 2 < nch) LOADC(s2);
        CP_COMMIT();

        // compute on stage s0
        #pragma unroll
        for (int ks = 0; ks < 2; ks++) {
            const uint32_t ab = s0 + (aoff ^ (ks << 5));
            const uint32_t bb = s0 + 16384 + (boff ^ (ks << 5));
            uint32_t ah[2][4], al[2][4];
            ldmx4(ah[0], ab);
            ldmx4(ah[1], ab + 1024);
            ldmx4(al[0], ab + 8192);
            ldmx4(al[1], ab + 8192 + 1024);
            #pragma unroll
            for (int p = 0; p < 4; p++) {
                uint32_t bh[4], bl[4];
                ldmx4(bh, bb + p * 1024);
                ldmx4(bl, bb + 8192 + p * 1024);
                #pragma unroll
                for (int mi = 0; mi < 2; mi++) {
                    mma16816(acc[mi][2 * p],     ah[mi], bh[0], bh[1]);
                    mma16816(acc[mi][2 * p + 1], ah[mi], bh[2], bh[3]);
                    mma16816(acc[mi][2 * p],     ah[mi], bl[0], bl[1]);
                    mma16816(acc[mi][2 * p + 1], ah[mi], bl[2], bl[3]);
                    mma16816(acc[mi][2 * p],     al[mi], bh[0], bh[1]);
                    mma16816(acc[mi][2 * p + 1], al[mi], bh[2], bh[3]);
                }
            }
        }
        // rotate stages
        uint32_t tmp = s0; s0 = s1; s1 = s2; s2 = tmp;
    }
#undef LOADC
}

// ---------------------------------------------------------------- split kernel
__global__ __launch_bounds__(NTH)
void split_kernel(const float* __restrict__ src, __nv_bfloat16* __restrict__ h,
                  __nv_bfloat16* __restrict__ l, int n4) {
    int i = blockIdx.x * NTH + threadIdx.x;
    if (i >= n4) return;
    float4 v = reinterpret_cast<const float4*>(src)[i];
    uint16_t h0, h1, h2, h3, l0, l1, l2, l3;
    split_bf16(v.x, h0, l0); split_bf16(v.y, h1, l1);
    split_bf16(v.z, h2, l2); split_bf16(v.w, h3, l3);
    reinterpret_cast<uint2*>(h)[i] =
        make_uint2((uint32_t)h0 | ((uint32_t)h1 << 16), (uint32_t)h2 | ((uint32_t)h3 << 16));
    reinterpret_cast<uint2*>(l)[i] =
        make_uint2((uint32_t)l0 | ((uint32_t)l1 << 16), (uint32_t)l2 | ((uint32_t)l3 << 16));
}

// transpose + split: out[i][j] = in[j][i], 512x512
__global__ __launch_bounds__(NTH)
void tsplit_kernel(const float* __restrict__ src, __nv_bfloat16* __restrict__ th,
                   __nv_bfloat16* __restrict__ tl) {
    __shared__ float tile[32][33];
    const int bx = blockIdx.x * 32, by = blockIdx.y * 32;
    const int tx = threadIdx.x & 31, ty = threadIdx.x >> 5;   // 8 rows of 32
    #pragma unroll
    for (int r = ty; r < 32; r += 8)
        tile[r][tx] = src[(size_t)(by + r) * DM + bx + tx];
    __syncthreads();
    #pragma unroll
    for (int r = ty; r < 32; r += 8) {
        float v = tile[tx][r];
        uint16_t h, l;
        split_bf16(v, h, l);
        th[(size_t)(bx + r) * DM + by + tx] = __ushort_as_bfloat16(h);
        tl[(size_t)(bx + r) * DM + by + tx] = __ushort_as_bfloat16(l);
    }
}

// ---------------------------------------------------------------- kernel: M^T = Wk^T * Wq (scaled)
__global__ __launch_bounds__(NTH, 2)
void mgemm_kernel() {
    extern __shared__ __align__(128) char smem[];
    const uint32_t sb = smem_u32(smem);
    const int t = threadIdx.x, wid = t >> 5, lane = t & 31;
    const int wr = wid & 3, wc = wid >> 2;
    const int m0 = blockIdx.y * BM;
    const int n0 = blockIdx.x * BN;

    float acc[2][8][4];
    #pragma unroll
    for (int a = 0; a < 2; a++)
        #pragma unroll
        for (int b = 0; b < 8; b++)
            #pragma unroll
            for (int r = 0; r < 4; r++) acc[a][b][r] = 0.0f;

    run_gemm(sb, t, wr, wc, lane,
             g_WkTh + (size_t)m0 * DM, g_WkTl + (size_t)m0 * DM,
             g_WqTh + (size_t)n0 * DM, g_WqTl + (size_t)n0 * DM,
             DM, DM, DM / BK, acc);

    #pragma unroll
    for (int mi = 0; mi < 2; mi++) {
        #pragma unroll
        for (int ni = 0; ni < 8; ni++) {
            int row = m0 + wr * 32 + mi * 16 + (lane >> 2);
            int col = n0 + wc * 64 + ni * 8 + ((lane & 3) << 1);
            uint16_t h0, h1, l0, l1;
            split_bf16(acc[mi][ni][0] * SOFTMAX_SCALE, h0, l0);
            split_bf16(acc[mi][ni][1] * SOFTMAX_SCALE, h1, l1);
            *reinterpret_cast<uint32_t*>(&g_MTh[(size_t)row * DM + col]) =
                (uint32_t)h0 | ((uint32_t)h1 << 16);
            *reinterpret_cast<uint32_t*>(&g_MTl[(size_t)row * DM + col]) =
                (uint32_t)l0 | ((uint32_t)l1 << 16);
            split_bf16(acc[mi][ni][2] * SOFTMAX_SCALE, h0, l0);
            split_bf16(acc[mi][ni][3] * SOFTMAX_SCALE, h1, l1);
            *reinterpret_cast<uint32_t*>(&g_MTh[(size_t)(row + 8) * DM + col]) =
                (uint32_t)h0 | ((uint32_t)h1 << 16);
            *reinterpret_cast<uint32_t*>(&g_MTl[(size_t)(row + 8) * DM + col]) =
                (uint32_t)l0 | ((uint32_t)l1 << 16);
        }
    }
}

// ---------------------------------------------------------------- kernel: proj (G and V)
__global__ __launch_bounds__(NTH, 2)
void proj_kernel() {
    extern __shared__ __align__(128) char smem[];
    const uint32_t sb = smem_u32(smem);
    const int t = threadIdx.x, wid = t >> 5, lane = t & 31;
    const int wr = wid & 3, wc = wid >> 2;
    const int which = blockIdx.z;
    const int m0 = blockIdx.y * BM;      // global row (b*SEQ+s)
    const int n0 = blockIdx.x * BN;

    float acc[2][8][4];
    #pragma unroll
    for (int a = 0; a < 2; a++)
        #pragma unroll
        for (int b = 0; b < 8; b++)
            #pragma unroll
            for (int r = 0; r < 4; r++) acc[a][b][r] = 0.0f;

    run_gemm(sb, t, wr, wc, lane,
             g_xh + (size_t)m0 * DM, g_xl + (size_t)m0 * DM,
             (which == 0 ? g_MTh : g_Wvh) + (size_t)n0 * DM,
             (which == 0 ? g_MTl : g_Wvl) + (size_t)n0 * DM,
             DM, DM, DM / BK, acc);

    if (which == 0) {
        #pragma unroll
        for (int mi = 0; mi < 2; mi++) {
            #pragma unroll
            for (int ni = 0; ni < 8; ni++) {
                int row = m0 + wr * 32 + mi * 16 + (lane >> 2);
                int col = n0 + wc * 64 + ni * 8 + ((lane & 3) << 1);
                uint16_t h0, h1, l0, l1;
                split_bf16(acc[mi][ni][0], h0, l0);
                split_bf16(acc[mi][ni][1], h1, l1);
                *reinterpret_cast<uint32_t*>(&g_Gh[(size_t)row * DM + col]) =
                    (uint32_t)h0 | ((uint32_t)h1 << 16);
                *reinterpret_cast<uint32_t*>(&g_Gl[(size_t)row * DM + col]) =
                    (uint32_t)l0 | ((uint32_t)l1 << 16);
                split_bf16(acc[mi][ni][2], h0, l0);
                split_bf16(acc[mi][ni][3], h1, l1);
                *reinterpret_cast<uint32_t*>(&g_Gh[(size_t)(row + 8) * DM + col]) =
                    (uint32_t)h0 | ((uint32_t)h1 << 16);
                *reinterpret_cast<uint32_t*>(&g_Gl[(size_t)(row + 8) * DM + col]) =
                    (uint32_t)l0 | ((uint32_t)l1 << 16);
            }
        }
    } else {
        // V: transpose through smem, write V^T hi/lo coalesced
        __syncthreads();
        #pragma unroll
        for (int mi = 0; mi < 2; mi++) {
            #pragma unroll
            for (int ni = 0; ni < 8; ni++) {
                #pragma unroll
                for (int r = 0; r < 4; r++) {
                    int srow = wr * 32 + mi * 16 + (lane >> 2) + ((r >> 1) << 3);
                    int dcol = wc * 64 + ni * 8 + ((lane & 3) << 1) + (r & 1);
                    uint16_t h, l;
                    split_bf16(acc[mi][ni][r], h, l);
                    *reinterpret_cast<uint16_t*>(smem + dcol * 256 + srow * 2) = h;
                    *reinterpret_cast<uint16_t*>(smem + 32768 + dcol * 256 + srow * 2) = l;
                }
            }
        }
        __syncthreads();
        const int b = m0 >> 12, s0r = m0 & (SEQ - 1);
        const int d = t >> 1, half = t & 1;
        const uint4* sh = reinterpret_cast<const uint4*>(smem + d * 256 + half * 128);
        const uint4* sl = reinterpret_cast<const uint4*>(smem + 32768 + d * 256 + half * 128);
        size_t o = ((size_t)b * DM + n0 + d) * SEQ + s0r + half * 64;
        uint4* dh = reinterpret_cast<uint4*>(g_Vth + o);
        uint4* dl = reinterpret_cast<uint4*>(g_Vtl + o);
        #pragma unroll
        for (int q = 0; q < 8; q++) { dh[q] = sh[q]; dl[q] = sl[q]; }
    }
}

// ---------------------------------------------------------------- kernel: scores  S = G x^T
__global__ __launch_bounds__(NTH, 2)
void scores_kernel(float* __restrict__ att) {
    const int kt = blockIdx.x, qt = blockIdx.y;
    const int b = blockIdx.z;
    float* __restrict__ attb = att + (size_t)b * SEQ * SEQ;
    const int t = threadIdx.x;

    if (kt > qt) {
        // fully masked tile: write zeros (covers poisoned upper triangle)
        int row = qt * BM + (t >> 1);
        int col = kt * BN + (t & 1) * 64;
        float4 z = make_float4(0.f, 0.f, 0.f, 0.f);
        float4* dst = reinterpret_cast<float4*>(&attb[(size_t)row * SEQ + col]);
        #pragma unroll
        for (int i = 0; i < 16; i++) dst[i] = z;
        return;
    }

    extern __shared__ __align__(128) char smem[];
    const uint32_t sb = smem_u32(smem);
    const int wid = t >> 5, lane = t & 31;
    const int wr = wid & 3, wc = wid >> 2;

    const size_t qr = ((size_t)b * SEQ + qt * BM) * DM;
    const size_t kr = ((size_t)b * SEQ + kt * BN) * DM;

    float acc[2][8][4];
    #pragma unroll
    for (int a = 0; a < 2; a++)
        #pragma unroll
        for (int c = 0; c < 8; c++)
            #pragma unroll
            for (int r = 0; r < 4; r++) acc[a][c][r] = 0.0f;

    run_gemm(sb, t, wr, wc, lane,
             g_Gh + qr, g_Gl + qr, g_xh + kr, g_xl + kr,
             DM, DM, DM / BK, acc);

    #pragma unroll
    for (int mi = 0; mi < 2; mi++) {
        #pragma unroll
        for (int ni = 0; ni < 8; ni++) {
            int row = qt * BM + wr * 32 + mi * 16 + (lane >> 2);
            int col = kt * BN + wc * 64 + ni * 8 + ((lane & 3) << 1);
            *reinterpret_cast<float2*>(&attb[(size_t)row * SEQ + col]) =
                make_float2(acc[mi][ni][0], acc[mi][ni][1]);
            *reinterpret_cast<float2*>(&attb[(size_t)(row + 8) * SEQ + col]) =
                make_float2(acc[mi][ni][2], acc[mi][ni][3]);
        }
    }
}

// ---------------------------------------------------------------- kernel: softmax (vectorized)
__global__ __launch_bounds__(NTH)
void softmax_kernel(float* __restrict__ att) {
    const int rr = blockIdx.x;
    const int b = rr >> 12;
    const int q = rr & (SEQ - 1);
    float* __restrict__ row = att + (size_t)b * SEQ * SEQ + (size_t)q * SEQ;
    __nv_bfloat16* __restrict__ ph = g_Ph + (size_t)b * SEQ * SEQ + (size_t)q * SEQ;
    __nv_bfloat16* __restrict__ pl = g_Pl + (size_t)b * SEQ * SEQ + (size_t)q * SEQ;
    const int L = q + 1;
    const int L4 = (L + 3) >> 2;
    const int jmax4 = (((q >> 7) + 1) << 7) >> 2;   // pad to 128-tile, /4

    __shared__ float4 sm4[SEQ / 4];
    __shared__ float red[NTH];
    const int t = threadIdx.x;

    float mx = -INFINITY;
    for (int j4 = t; j4 < L4; j4 += NTH) {
        float4 v = reinterpret_cast<const float4*>(row)[j4];
        int base = j4 << 2;
        float m1 = (base + 1 < L) ? v.y : -INFINITY;
        float m2 = (base + 2 < L) ? v.z : -INFINITY;
        float m3 = (base + 3 < L) ? v.w : -INFINITY;
        mx = fmaxf(mx, fmaxf(fmaxf(v.x, m1), fmaxf(m2, m3)));
        sm4[j4] = v;
    }
    red[t] = mx;
    __syncthreads();
    #pragma unroll
    for (int s = NTH / 2; s > 0; s >>= 1) {
        if (t < s) red[t] = fmaxf(red[t], red[t + s]);
        __syncthreads();
    }
    const float rowmax = red[0];
    __syncthreads();

    float sum = 0.0f;
    for (int j4 = t; j4 < L4; j4 += NTH) {
        float4 v = sm4[j4];
        int base = j4 << 2;
        float e0 = __expf(v.x - rowmax);
        float e1 = (base + 1 < L) ? __expf(v.y - rowmax) : 0.0f;
        float e2 = (base + 2 < L) ? __expf(v.z - rowmax) : 0.0f;
        float e3 = (base + 3 < L) ? __expf(v.w - rowmax) : 0.0f;
        sm4[j4] = make_float4(e0, e1, e2, e3);
        sum += (e0 + e1) + (e2 + e3);
    }
    red[t] = sum;
    __syncthreads();
    #pragma unroll
    for (int s = NTH / 2; s > 0; s >>= 1) {
        if (t < s) red[t] += red[t + s];
        __syncthreads();
    }
    const float inv = 1.0f / red[0];

    for (int j4 = t; j4 < jmax4; j4 += NTH) {
        float4 v = (j4 < L4) ? sm4[j4] : make_float4(0.f, 0.f, 0.f, 0.f);
        float4 o = make_float4(v.x * inv, v.y * inv, v.z * inv, v.w * inv);
        reinterpret_cast<float4*>(row)[j4] = o;
        uint16_t h0, h1, h2, h3, l0, l1, l2, l3;
        split_bf16(o.x, h0, l0); split_bf16(o.y, h1, l1);
        split_bf16(o.z, h2, l2); split_bf16(o.w, h3, l3);
        reinterpret_cast<uint2*>(ph)[j4] =
            make_uint2((uint32_t)h0 | ((uint32_t)h1 << 16), (uint32_t)h2 | ((uint32_t)h3 << 16));
        reinterpret_cast<uint2*>(pl)[j4] =
            make_uint2((uint32_t)l0 | ((uint32_t)l1 << 16), (uint32_t)l2 | ((uint32_t)l3 << 16));
    }
}

// ---------------------------------------------------------------- kernel: AV + residual
__global__ __launch_bounds__(NTH, 2)
void av_kernel(const float* __restrict__ x, float* __restrict__ out) {
    const int b = blockIdx.z;
    const int qt = blockIdx.y;
    const int n0 = blockIdx.x * BN;
    const int m0 = qt * BM;              // batch-local q row

    extern __shared__ __align__(128) char smem[];
    const uint32_t sb = smem_u32(smem);
    const int t = threadIdx.x, wid = t >> 5, lane = t & 31;
    const int wr = wid & 3, wc = wid >> 2;

    const size_t pr = ((size_t)b * SEQ + m0) * SEQ;
    const size_t vr = ((size_t)b * DM + n0) * SEQ;

    float acc[2][8][4];
    #pragma unroll
    for (int a = 0; a < 2; a++)
        #pragma unroll
        for (int c = 0; c < 8; c++)
            #pragma unroll
            for (int r = 0; r < 4; r++) acc[a][c][r] = 0.0f;

    const int nch = ((qt + 1) * BM) / BK;   // causal truncation

    run_gemm(sb, t, wr, wc, lane,
             g_Ph + pr, g_Pl + pr, g_Vth + vr, g_Vtl + vr,
             SEQ, SEQ, nch, acc);

    #pragma unroll
    for (int mi = 0; mi < 2; mi++) {
        #pragma unroll
        for (int ni = 0; ni < 8; ni++) {
            int row = m0 + wr * 32 + mi * 16 + (lane >> 2);
            int col = n0 + wc * 64 + ni * 8 + ((lane & 3) << 1);
            size_t base = ((size_t)b * SEQ + row) * DM + col;
            float2 xv = *reinterpret_cast<const float2*>(&x[base]);
            *reinterpret_cast<float2*>(&out[base]) =
                make_float2(acc[mi][ni][0] + xv.x, acc[mi][ni][1] + xv.y);
            size_t base8 = base + (size_t)8 * DM;
            float2 xv8 = *reinterpret_cast<const float2*>(&x[base8]);
            *reinterpret_cast<float2*>(&out[base8]) =
                make_float2(acc[mi][ni][2] + xv8.x, acc[mi][ni][3] + xv8.y);
        }
    }
}

// ---------------------------------------------------------------- launch
extern "C" void kernel_launch(void* const* d_in, const int* in_sizes, int n_in,
                              void* d_out, int out_size) {
    const float* x  = (const float*)d_in[0];
    const float* WQ = (const float*)d_in[1];
    const float* WK = (const float*)d_in[2];
    const float* WV = (const float*)d_in[3];

    float* out = (float*)d_out;                   // [B,S,D]
    float* att = out + (size_t)BSZ * SEQ * DM;    // [B,S,S]

    cudaFuncSetAttribute(mgemm_kernel,  cudaFuncAttributeMaxDynamicSharedMemorySize, SMEM_TOTAL);
    cudaFuncSetAttribute(proj_kernel,   cudaFuncAttributeMaxDynamicSharedMemorySize, SMEM_TOTAL);
    cudaFuncSetAttribute(scores_kernel, cudaFuncAttributeMaxDynamicSharedMemorySize, SMEM_TOTAL);
    cudaFuncSetAttribute(av_kernel,     cudaFuncAttributeMaxDynamicSharedMemorySize, SMEM_TOTAL);

    __nv_bfloat16 *xh, *xl, *wqth, *wqtl, *wkth, *wktl, *wvh, *wvl;
    cudaGetSymbolAddress((void**)&xh, g_xh);
    cudaGetSymbolAddress((void**)&xl, g_xl);
    cudaGetSymbolAddress((void**)&wqth, g_WqTh);
    cudaGetSymbolAddress((void**)&wqtl, g_WqTl);
    cudaGetSymbolAddress((void**)&wkth, g_WkTh);
    cudaGetSymbolAddress((void**)&wktl, g_WkTl);
    cudaGetSymbolAddress((void**)&wvh, g_Wvh);
    cudaGetSymbolAddress((void**)&wvl, g_Wvl);

    // 0) splits / transposed splits
    split_kernel<<<(NROWS * DM / 4 + NTH - 1) / NTH, NTH>>>(x, xh, xl, NROWS * DM / 4);
    split_kernel<<<(DM * DM / 4 + NTH - 1) / NTH, NTH>>>(WV, wvh, wvl, DM * DM / 4);
    dim3 gt(DM / 32, DM / 32);
    tsplit_kernel<<<gt, NTH>>>(WQ, wqth, wqtl);
    tsplit_kernel<<<gt, NTH>>>(WK, wkth, wktl);

    // 1) M^T = scale * Wk^T Wq  (512x512)
    dim3 gm(DM / BN, DM / BM);
    mgemm_kernel<<<gm, NTH, SMEM_TOTAL>>>();

    // 2) G = x M (scale folded), V = x Wv^T (transposed)
    dim3 g1(DM / BN, NROWS / BM, 2);
    proj_kernel<<<g1, NTH, SMEM_TOTAL>>>();

    // 3) causal scores S = G x^T; masked tiles zero-filled
    dim3 g2(SEQ / BN, SEQ / BM, BSZ);
    scores_kernel<<<g2, NTH, SMEM_TOTAL>>>(att);

    // 4) softmax: fp32 probs to d_out, bf16 hi/lo probs to scratch
    softmax_kernel<<<NROWS, NTH>>>(att);

    // 5) O = P @ V + x
    dim3 g4(DM / BN, SEQ / BM, BSZ);
    av_kernel<<<g4, NTH, SMEM_TOTAL>>>(x, out);
}

// round 10
// speedup vs baseline: 1.4081x; 1.1128x over previous
#include <cuda_runtime.h>
#include <cuda_bf16.h>
#include <math.h>
#include <stdint.h>

// ---------------------------------------------------------------- dims
#define BSZ 4
#define SEQ 4096
#define DM  512
#define NROWS (BSZ * SEQ)                 // 16384
#define NTH 256
#define BM 128
#define BN 128
#define BK 32
#define SOFTMAX_SCALE 0.04419417382415922f

// smem stage layout (bf16 tiles, 64-byte rows, SW64 swizzle)
// regions within a stage: AH 0, AL 8192, BH 16384, BL 24576
#define STAGE 32768
#define NSTAGE 3
#define SMEM_TOTAL (NSTAGE * STAGE)       // 98304 bytes -> 2 CTAs/SM

#define SW64(o) ((uint32_t)(o) ^ ((((uint32_t)(o)) >> 3) & 0x30u))

// ---------------------------------------------------------------- scratch
__device__ __nv_bfloat16 g_xh[(size_t)NROWS * DM];
__device__ __nv_bfloat16 g_xl[(size_t)NROWS * DM];
__device__ __nv_bfloat16 g_WqTh[DM * DM];   // Wq^T  [d][f]
__device__ __nv_bfloat16 g_WqTl[DM * DM];
__device__ __nv_bfloat16 g_WkTh[DM * DM];   // Wk^T  [e][f]
__device__ __nv_bfloat16 g_WkTl[DM * DM];
__device__ __nv_bfloat16 g_Wvh[DM * DM];    // Wv    [e][d]
__device__ __nv_bfloat16 g_Wvl[DM * DM];
__device__ __nv_bfloat16 g_MTh[DM * DM];    // (Wq^T Wk)^T * scale  [e][d]
__device__ __nv_bfloat16 g_MTl[DM * DM];
__device__ __nv_bfloat16 g_Gh[(size_t)NROWS * DM];   // G = x*M*scale
__device__ __nv_bfloat16 g_Gl[(size_t)NROWS * DM];
__device__ __nv_bfloat16 g_Vth[(size_t)BSZ * DM * SEQ];  // V^T [b][d][s]
__device__ __nv_bfloat16 g_Vtl[(size_t)BSZ * DM * SEQ];
__device__ __nv_bfloat16 g_Ph[(size_t)BSZ * SEQ * SEQ];  // probs hi/lo
__device__ __nv_bfloat16 g_Pl[(size_t)BSZ * SEQ * SEQ];

// ---------------------------------------------------------------- helpers
__device__ __forceinline__ uint32_t smem_u32(const void* p) {
    return (uint32_t)__cvta_generic_to_shared(p);
}
__device__ __forceinline__ void ldmx4(uint32_t r[4], uint32_t addr) {
    asm volatile("ldmatrix.sync.aligned.m8n8.x4.shared.b16 {%0,%1,%2,%3}, [%4];"
                 : "=r"(r[0]), "=r"(r[1]), "=r"(r[2]), "=r"(r[3]) : "r"(addr));
}
__device__ __forceinline__ void mma16816(float d[4], const uint32_t a[4],
                                         uint32_t b0, uint32_t b1) {
    asm volatile("mma.sync.aligned.m16n8k16.row.col.f32.bf16.bf16.f32 "
                 "{%0,%1,%2,%3}, {%4,%5,%6,%7}, {%8,%9}, {%0,%1,%2,%3};"
                 : "+f"(d[0]), "+f"(d[1]), "+f"(d[2]), "+f"(d[3])
                 : "r"(a[0]), "r"(a[1]), "r"(a[2]), "r"(a[3]), "r"(b0), "r"(b1));
}
__device__ __forceinline__ void cpasync16(uint32_t dst, const void* src) {
    asm volatile("cp.async.cg.shared.global [%0], [%1], 16;" :: "r"(dst), "l"(src));
}
#define CP_COMMIT() asm volatile("cp.async.commit_group;")
#define CP_WAIT(N)  asm volatile("cp.async.wait_group %0;" :: "n"(N))

__device__ __forceinline__ void split_bf16(float v, uint16_t& h, uint16_t& l) {
    __nv_bfloat16 hb = __float2bfloat16(v);
    float r = v - __bfloat162float(hb);
    h = __bfloat16_as_ushort(hb);
    l = __bfloat16_as_ushort(__float2bfloat16(r));
}

// ---------------------------------------------------------------- GEMM engine
// Strength-reduced pipeline: all smem addresses are (2 base offsets + imm).
// ks step uses XOR (swizzle-correct since base column bit5 is clear);
// row steps (+1024, +4096) and region offsets never touch swizzle keys.
// acc += Ah*Bh + Ah*Bl + Al*Bh over nch chunks of BK=32.
__device__ __forceinline__ void run_gemm(
    uint32_t sb, int t, int wr, int wc, int lane,
    const __nv_bfloat16* Ah, const __nv_bfloat16* Al,
    const __nv_bfloat16* Bh, const __nv_bfloat16* Bl,
    size_t ldA, size_t ldB, int nch, float acc[2][8][4])
{
    // per-thread cp.async mapping: row = t>>2 (0..63), elem col = (t&3)*8;
    // second vector at row+64 -> smem offset +4096 (swizzle-invariant).
    const int lrow = t >> 2;
    const int lc8 = (t & 3) << 3;
    const uint32_t sdst = SW64((lrow << 6) + (lc8 << 1));
    const __nv_bfloat16* pAh = Ah + (size_t)lrow * ldA + lc8;
    const __nv_bfloat16* pAl = Al + (size_t)lrow * ldA + lc8;
    const __nv_bfloat16* pBh = Bh + (size_t)lrow * ldB + lc8;
    const __nv_bfloat16* pBl = Bl + (size_t)lrow * ldB + lc8;
    const size_t a64 = (size_t)64 * ldA;
    const size_t b64 = (size_t)64 * ldB;

    // ldmatrix base offsets (raw column byte has bit5 clear -> ks via XOR 32)
    const uint32_t aoff = SW64(((wr * 32 + (lane & 15)) << 6) + (((lane >> 4) << 3) << 1));
    const uint32_t boff = SW64(((wc * 64 + ((lane >> 4) << 3) + (lane & 7)) << 6)
                               + ((((lane >> 3) & 1) << 3) << 1));

    uint32_t s0 = sb, s1 = sb + STAGE, s2 = sb + 2 * STAGE;

#define LOADC(d)                                                                  \
    do {                                                                          \
        cpasync16((d) + sdst,                 pAh);                               \
        cpasync16((d) + sdst + 4096,          pAh + a64);                         \
        cpasync16((d) + 8192 + sdst,          pAl);                               \
        cpasync16((d) + 8192 + sdst + 4096,   pAl + a64);                         \
        cpasync16((d) + 16384 + sdst,         pBh);                               \
        cpasync16((d) + 16384 + sdst + 4096,  pBh + b64);                         \
        cpasync16((d) + 24576 + sdst,         pBl);                               \
        cpasync16((d) + 24576 + sdst + 4096,  pBl + b64);                         \
        pAh += BK; pAl += BK; pBh += BK; pBl += BK;                               \
    } while (0)

    LOADC(s0);
    CP_COMMIT();
    if (nch > 1) LOADC(s1);
    CP_COMMIT();

    for (int c = 0; c < nch; c++) {
        CP_WAIT(1);
        __syncthreads();
        if (c + 2 < nch) LOADC(s2);
        CP_COMMIT();

        // compute on stage s0
        #pragma unroll
        for (int ks = 0; ks < 2; ks++) {
            const uint32_t ab = s0 + (aoff ^ (ks << 5));
            const uint32_t bb = s0 + 16384 + (boff ^ (ks << 5));
            uint32_t ah[2][4], al[2][4];
            ldmx4(ah[0], ab);
            ldmx4(ah[1], ab + 1024);
            ldmx4(al[0], ab + 8192);
            ldmx4(al[1], ab + 8192 + 1024);
            #pragma unroll
            for (int p = 0; p < 4; p++) {
                uint32_t bh[4], bl[4];
                ldmx4(bh, bb + p * 1024);
                ldmx4(bl, bb + 8192 + p * 1024);
                #pragma unroll
                for (int mi = 0; mi < 2; mi++) {
                    mma16816(acc[mi][2 * p],     ah[mi], bh[0], bh[1]);
                    mma16816(acc[mi][2 * p + 1], ah[mi], bh[2], bh[3]);
                    mma16816(acc[mi][2 * p],     ah[mi], bl[0], bl[1]);
                    mma16816(acc[mi][2 * p + 1], ah[mi], bl[2], bl[3]);
                    mma16816(acc[mi][2 * p],     al[mi], bh[0], bh[1]);
                    mma16816(acc[mi][2 * p + 1], al[mi], bh[2], bh[3]);
                }
            }
        }
        // rotate stages
        uint32_t tmp = s0; s0 = s1; s1 = s2; s2 = tmp;
    }
#undef LOADC
}

// ---------------------------------------------------------------- split kernel
__global__ __launch_bounds__(NTH)
void split_kernel(const float* __restrict__ src, __nv_bfloat16* __restrict__ h,
                  __nv_bfloat16* __restrict__ l, int n4) {
    int i = blockIdx.x * NTH + threadIdx.x;
    if (i >= n4) return;
    float4 v = reinterpret_cast<const float4*>(src)[i];
    uint16_t h0, h1, h2, h3, l0, l1, l2, l3;
    split_bf16(v.x, h0, l0); split_bf16(v.y, h1, l1);
    split_bf16(v.z, h2, l2); split_bf16(v.w, h3, l3);
    reinterpret_cast<uint2*>(h)[i] =
        make_uint2((uint32_t)h0 | ((uint32_t)h1 << 16), (uint32_t)h2 | ((uint32_t)h3 << 16));
    reinterpret_cast<uint2*>(l)[i] =
        make_uint2((uint32_t)l0 | ((uint32_t)l1 << 16), (uint32_t)l2 | ((uint32_t)l3 << 16));
}

// prefill: out = x (residual base for split-K atomic accumulation)
__global__ __launch_bounds__(NTH)
void prefill_kernel(const float* __restrict__ x, float* __restrict__ out, int n4) {
    int i = blockIdx.x * NTH + threadIdx.x;
    if (i >= n4) return;
    reinterpret_cast<float4*>(out)[i] = reinterpret_cast<const float4*>(x)[i];
}

// transpose + split: out[i][j] = in[j][i], 512x512
__global__ __launch_bounds__(NTH)
void tsplit_kernel(const float* __restrict__ src, __nv_bfloat16* __restrict__ th,
                   __nv_bfloat16* __restrict__ tl) {
    __shared__ float tile[32][33];
    const int bx = blockIdx.x * 32, by = blockIdx.y * 32;
    const int tx = threadIdx.x & 31, ty = threadIdx.x >> 5;   // 8 rows of 32
    #pragma unroll
    for (int r = ty; r < 32; r += 8)
        tile[r][tx] = src[(size_t)(by + r) * DM + bx + tx];
    __syncthreads();
    #pragma unroll
    for (int r = ty; r < 32; r += 8) {
        float v = tile[tx][r];
        uint16_t h, l;
        split_bf16(v, h, l);
        th[(size_t)(bx + r) * DM + by + tx] = __ushort_as_bfloat16(h);
        tl[(size_t)(bx + r) * DM + by + tx] = __ushort_as_bfloat16(l);
    }
}

// ---------------------------------------------------------------- kernel: M^T = Wk^T * Wq (scaled)
__global__ __launch_bounds__(NTH, 2)
void mgemm_kernel() {
    extern __shared__ __align__(128) char smem[];
    const uint32_t sb = smem_u32(smem);
    const int t = threadIdx.x, wid = t >> 5, lane = t & 31;
    const int wr = wid & 3, wc = wid >> 2;
    const int m0 = blockIdx.y * BM;
    const int n0 = blockIdx.x * BN;

    float acc[2][8][4];
    #pragma unroll
    for (int a = 0; a < 2; a++)
        #pragma unroll
        for (int b = 0; b < 8; b++)
            #pragma unroll
            for (int r = 0; r < 4; r++) acc[a][b][r] = 0.0f;

    run_gemm(sb, t, wr, wc, lane,
             g_WkTh + (size_t)m0 * DM, g_WkTl + (size_t)m0 * DM,
             g_WqTh + (size_t)n0 * DM, g_WqTl + (size_t)n0 * DM,
             DM, DM, DM / BK, acc);

    #pragma unroll
    for (int mi = 0; mi < 2; mi++) {
        #pragma unroll
        for (int ni = 0; ni < 8; ni++) {
            int row = m0 + wr * 32 + mi * 16 + (lane >> 2);
            int col = n0 + wc * 64 + ni * 8 + ((lane & 3) << 1);
            uint16_t h0, h1, l0, l1;
            split_bf16(acc[mi][ni][0] * SOFTMAX_SCALE, h0, l0);
            split_bf16(acc[mi][ni][1] * SOFTMAX_SCALE, h1, l1);
            *reinterpret_cast<uint32_t*>(&g_MTh[(size_t)row * DM + col]) =
                (uint32_t)h0 | ((uint32_t)h1 << 16);
            *reinterpret_cast<uint32_t*>(&g_MTl[(size_t)row * DM + col]) =
                (uint32_t)l0 | ((uint32_t)l1 << 16);
            split_bf16(acc[mi][ni][2] * SOFTMAX_SCALE, h0, l0);
            split_bf16(acc[mi][ni][3] * SOFTMAX_SCALE, h1, l1);
            *reinterpret_cast<uint32_t*>(&g_MTh[(size_t)(row + 8) * DM + col]) =
                (uint32_t)h0 | ((uint32_t)h1 << 16);
            *reinterpret_cast<uint32_t*>(&g_MTl[(size_t)(row + 8) * DM + col]) =
                (uint32_t)l0 | ((uint32_t)l1 << 16);
        }
    }
}

// ---------------------------------------------------------------- kernel: proj (G and V)
__global__ __launch_bounds__(NTH, 2)
void proj_kernel() {
    extern __shared__ __align__(128) char smem[];
    const uint32_t sb = smem_u32(smem);
    const int t = threadIdx.x, wid = t >> 5, lane = t & 31;
    const int wr = wid & 3, wc = wid >> 2;
    const int which = blockIdx.z;
    const int m0 = blockIdx.y * BM;      // global row (b*SEQ+s)
    const int n0 = blockIdx.x * BN;

    float acc[2][8][4];
    #pragma unroll
    for (int a = 0; a < 2; a++)
        #pragma unroll
        for (int b = 0; b < 8; b++)
            #pragma unroll
            for (int r = 0; r < 4; r++) acc[a][b][r] = 0.0f;

    run_gemm(sb, t, wr, wc, lane,
             g_xh + (size_t)m0 * DM, g_xl + (size_t)m0 * DM,
             (which == 0 ? g_MTh : g_Wvh) + (size_t)n0 * DM,
             (which == 0 ? g_MTl : g_Wvl) + (size_t)n0 * DM,
             DM, DM, DM / BK, acc);

    if (which == 0) {
        #pragma unroll
        for (int mi = 0; mi < 2; mi++) {
            #pragma unroll
            for (int ni = 0; ni < 8; ni++) {
                int row = m0 + wr * 32 + mi * 16 + (lane >> 2);
                int col = n0 + wc * 64 + ni * 8 + ((lane & 3) << 1);
                uint16_t h0, h1, l0, l1;
                split_bf16(acc[mi][ni][0], h0, l0);
                split_bf16(acc[mi][ni][1], h1, l1);
                *reinterpret_cast<uint32_t*>(&g_Gh[(size_t)row * DM + col]) =
                    (uint32_t)h0 | ((uint32_t)h1 << 16);
                *reinterpret_cast<uint32_t*>(&g_Gl[(size_t)row * DM + col]) =
                    (uint32_t)l0 | ((uint32_t)l1 << 16);
                split_bf16(acc[mi][ni][2], h0, l0);
                split_bf16(acc[mi][ni][3], h1, l1);
                *reinterpret_cast<uint32_t*>(&g_Gh[(size_t)(row + 8) * DM + col]) =
                    (uint32_t)h0 | ((uint32_t)h1 << 16);
                *reinterpret_cast<uint32_t*>(&g_Gl[(size_t)(row + 8) * DM + col]) =
                    (uint32_t)l0 | ((uint32_t)l1 << 16);
            }
        }
    } else {
        // V: transpose through smem, write V^T hi/lo coalesced
        __syncthreads();
        #pragma unroll
        for (int mi = 0; mi < 2; mi++) {
            #pragma unroll
            for (int ni = 0; ni < 8; ni++) {
                #pragma unroll
                for (int r = 0; r < 4; r++) {
                    int srow = wr * 32 + mi * 16 + (lane >> 2) + ((r >> 1) << 3);
                    int dcol = wc * 64 + ni * 8 + ((lane & 3) << 1) + (r & 1);
                    uint16_t h, l;
                    split_bf16(acc[mi][ni][r], h, l);
                    *reinterpret_cast<uint16_t*>(smem + dcol * 256 + srow * 2) = h;
                    *reinterpret_cast<uint16_t*>(smem + 32768 + dcol * 256 + srow * 2) = l;
                }
            }
        }
        __syncthreads();
        const int b = m0 >> 12, s0r = m0 & (SEQ - 1);
        const int d = t >> 1, half = t & 1;
        const uint4* sh = reinterpret_cast<const uint4*>(smem + d * 256 + half * 128);
        const uint4* sl = reinterpret_cast<const uint4*>(smem + 32768 + d * 256 + half * 128);
        size_t o = ((size_t)b * DM + n0 + d) * SEQ + s0r + half * 64;
        uint4* dh = reinterpret_cast<uint4*>(g_Vth + o);
        uint4* dl = reinterpret_cast<uint4*>(g_Vtl + o);
        #pragma unroll
        for (int q = 0; q < 8; q++) { dh[q] = sh[q]; dl[q] = sl[q]; }
    }
}

// ---------------------------------------------------------------- kernel: scores  S = G x^T
__global__ __launch_bounds__(NTH, 2)
void scores_kernel(float* __restrict__ att) {
    const int kt = blockIdx.x, qt = blockIdx.y;
    const int b = blockIdx.z;
    float* __restrict__ attb = att + (size_t)b * SEQ * SEQ;
    const int t = threadIdx.x;

    if (kt > qt) {
        // fully masked tile: write zeros (covers poisoned upper triangle)
        int row = qt * BM + (t >> 1);
        int col = kt * BN + (t & 1) * 64;
        float4 z = make_float4(0.f, 0.f, 0.f, 0.f);
        float4* dst = reinterpret_cast<float4*>(&attb[(size_t)row * SEQ + col]);
        #pragma unroll
        for (int i = 0; i < 16; i++) dst[i] = z;
        return;
    }

    extern __shared__ __align__(128) char smem[];
    const uint32_t sb = smem_u32(smem);
    const int wid = t >> 5, lane = t & 31;
    const int wr = wid & 3, wc = wid >> 2;

    const size_t qr = ((size_t)b * SEQ + qt * BM) * DM;
    const size_t kr = ((size_t)b * SEQ + kt * BN) * DM;

    float acc[2][8][4];
    #pragma unroll
    for (int a = 0; a < 2; a++)
        #pragma unroll
        for (int c = 0; c < 8; c++)
            #pragma unroll
            for (int r = 0; r < 4; r++) acc[a][c][r] = 0.0f;

    run_gemm(sb, t, wr, wc, lane,
             g_Gh + qr, g_Gl + qr, g_xh + kr, g_xl + kr,
             DM, DM, DM / BK, acc);

    #pragma unroll
    for (int mi = 0; mi < 2; mi++) {
        #pragma unroll
        for (int ni = 0; ni < 8; ni++) {
            int row = qt * BM + wr * 32 + mi * 16 + (lane >> 2);
            int col = kt * BN + wc * 64 + ni * 8 + ((lane & 3) << 1);
            *reinterpret_cast<float2*>(&attb[(size_t)row * SEQ + col]) =
                make_float2(acc[mi][ni][0], acc[mi][ni][1]);
            *reinterpret_cast<float2*>(&attb[(size_t)(row + 8) * SEQ + col]) =
                make_float2(acc[mi][ni][2], acc[mi][ni][3]);
        }
    }
}

// ---------------------------------------------------------------- kernel: softmax (vectorized)
__global__ __launch_bounds__(NTH)
void softmax_kernel(float* __restrict__ att) {
    const int rr = blockIdx.x;
    const int b = rr >> 12;
    const int q = rr & (SEQ - 1);
    float* __restrict__ row = att + (size_t)b * SEQ * SEQ + (size_t)q * SEQ;
    __nv_bfloat16* __restrict__ ph = g_Ph + (size_t)b * SEQ * SEQ + (size_t)q * SEQ;
    __nv_bfloat16* __restrict__ pl = g_Pl + (size_t)b * SEQ * SEQ + (size_t)q * SEQ;
    const int L = q + 1;
    const int L4 = (L + 3) >> 2;
    const int jmax4 = (((q >> 7) + 1) << 7) >> 2;   // pad to 128-tile, /4

    __shared__ float4 sm4[SEQ / 4];
    __shared__ float red[NTH];
    const int t = threadIdx.x;

    float mx = -INFINITY;
    for (int j4 = t; j4 < L4; j4 += NTH) {
        float4 v = reinterpret_cast<const float4*>(row)[j4];
        int base = j4 << 2;
        float m1 = (base + 1 < L) ? v.y : -INFINITY;
        float m2 = (base + 2 < L) ? v.z : -INFINITY;
        float m3 = (base + 3 < L) ? v.w : -INFINITY;
        mx = fmaxf(mx, fmaxf(fmaxf(v.x, m1), fmaxf(m2, m3)));
        sm4[j4] = v;
    }
    red[t] = mx;
    __syncthreads();
    #pragma unroll
    for (int s = NTH / 2; s > 0; s >>= 1) {
        if (t < s) red[t] = fmaxf(red[t], red[t + s]);
        __syncthreads();
    }
    const float rowmax = red[0];
    __syncthreads();

    float sum = 0.0f;
    for (int j4 = t; j4 < L4; j4 += NTH) {
        float4 v = sm4[j4];
        int base = j4 << 2;
        float e0 = __expf(v.x - rowmax);
        float e1 = (base + 1 < L) ? __expf(v.y - rowmax) : 0.0f;
        float e2 = (base + 2 < L) ? __expf(v.z - rowmax) : 0.0f;
        float e3 = (base + 3 < L) ? __expf(v.w - rowmax) : 0.0f;
        sm4[j4] = make_float4(e0, e1, e2, e3);
        sum += (e0 + e1) + (e2 + e3);
    }
    red[t] = sum;
    __syncthreads();
    #pragma unroll
    for (int s = NTH / 2; s > 0; s >>= 1) {
        if (t < s) red[t] += red[t + s];
        __syncthreads();
    }
    const float inv = 1.0f / red[0];

    for (int j4 = t; j4 < jmax4; j4 += NTH) {
        float4 v = (j4 < L4) ? sm4[j4] : make_float4(0.f, 0.f, 0.f, 0.f);
        float4 o = make_float4(v.x * inv, v.y * inv, v.z * inv, v.w * inv);
        reinterpret_cast<float4*>(row)[j4] = o;
        uint16_t h0, h1, h2, h3, l0, l1, l2, l3;
        split_bf16(o.x, h0, l0); split_bf16(o.y, h1, l1);
        split_bf16(o.z, h2, l2); split_bf16(o.w, h3, l3);
        reinterpret_cast<uint2*>(ph)[j4] =
            make_uint2((uint32_t)h0 | ((uint32_t)h1 << 16), (uint32_t)h2 | ((uint32_t)h3 << 16));
        reinterpret_cast<uint2*>(pl)[j4] =
            make_uint2((uint32_t)l0 | ((uint32_t)l1 << 16), (uint32_t)l2 | ((uint32_t)l3 << 16));
    }
}

// ---------------------------------------------------------------- kernel: AV split-K (atomic accumulate into out = x)
__global__ __launch_bounds__(NTH, 2)
void av_kernel(float* __restrict__ out) {
    const int b = blockIdx.z;
    const int qt = blockIdx.y >> 2;
    const int seg = blockIdx.y & 3;
    const int n0 = blockIdx.x * BN;
    const int m0 = qt * BM;              // batch-local q row

    const int nch = 4 * (qt + 1);        // total causal chunks for this q tile
    const int c0 = seg * 32;
    if (c0 >= nch) return;               // empty split
    const int nloc = min(32, nch - c0);

    extern __shared__ __align__(128) char smem[];
    const uint32_t sb = smem_u32(smem);
    const int t = threadIdx.x, wid = t >> 5, lane = t & 31;
    const int wr = wid & 3, wc = wid >> 2;

    const size_t pr = ((size_t)b * SEQ + m0) * SEQ + (size_t)c0 * BK;
    const size_t vr = ((size_t)b * DM + n0) * SEQ + (size_t)c0 * BK;

    float acc[2][8][4];
    #pragma unroll
    for (int a = 0; a < 2; a++)
        #pragma unroll
        for (int c = 0; c < 8; c++)
            #pragma unroll
            for (int r = 0; r < 4; r++) acc[a][c][r] = 0.0f;

    run_gemm(sb, t, wr, wc, lane,
             g_Ph + pr, g_Pl + pr, g_Vth + vr, g_Vtl + vr,
             SEQ, SEQ, nloc, acc);

    #pragma unroll
    for (int mi = 0; mi < 2; mi++) {
        #pragma unroll
        for (int ni = 0; ni < 8; ni++) {
            int row = m0 + wr * 32 + mi * 16 + (lane >> 2);
            int col = n0 + wc * 64 + ni * 8 + ((lane & 3) << 1);
            size_t base = ((size_t)b * SEQ + row) * DM + col;
            atomicAdd(&out[base],     acc[mi][ni][0]);
            atomicAdd(&out[base + 1], acc[mi][ni][1]);
            size_t base8 = base + (size_t)8 * DM;
            atomicAdd(&out[base8],     acc[mi][ni][2]);
            atomicAdd(&out[base8 + 1], acc[mi][ni][3]);
        }
    }
}

// ---------------------------------------------------------------- launch
extern "C" void kernel_launch(void* const* d_in, const int* in_sizes, int n_in,
                              void* d_out, int out_size) {
    const float* x  = (const float*)d_in[0];
    const float* WQ = (const float*)d_in[1];
    const float* WK = (const float*)d_in[2];
    const float* WV = (const float*)d_in[3];

    float* out = (float*)d_out;                   // [B,S,D]
    float* att = out + (size_t)BSZ * SEQ * DM;    // [B,S,S]

    cudaFuncSetAttribute(mgemm_kernel,  cudaFuncAttributeMaxDynamicSharedMemorySize, SMEM_TOTAL);
    cudaFuncSetAttribute(proj_kernel,   cudaFuncAttributeMaxDynamicSharedMemorySize, SMEM_TOTAL);
    cudaFuncSetAttribute(scores_kernel, cudaFuncAttributeMaxDynamicSharedMemorySize, SMEM_TOTAL);
    cudaFuncSetAttribute(av_kernel,     cudaFuncAttributeMaxDynamicSharedMemorySize, SMEM_TOTAL);

    __nv_bfloat16 *xh, *xl, *wqth, *wqtl, *wkth, *wktl, *wvh, *wvl;
    cudaGetSymbolAddress((void**)&xh, g_xh);
    cudaGetSymbolAddress((void**)&xl, g_xl);
    cudaGetSymbolAddress((void**)&wqth, g_WqTh);
    cudaGetSymbolAddress((void**)&wqtl, g_WqTl);
    cudaGetSymbolAddress((void**)&wkth, g_WkTh);
    cudaGetSymbolAddress((void**)&wktl, g_WkTl);
    cudaGetSymbolAddress((void**)&wvh, g_Wvh);
    cudaGetSymbolAddress((void**)&wvl, g_Wvl);

    // 0) splits / transposed splits; prefill out = x for split-K accumulation
    split_kernel<<<(NROWS * DM / 4 + NTH - 1) / NTH, NTH>>>(x, xh, xl, NROWS * DM / 4);
    split_kernel<<<(DM * DM / 4 + NTH - 1) / NTH, NTH>>>(WV, wvh, wvl, DM * DM / 4);
    dim3 gt(DM / 32, DM / 32);
    tsplit_kernel<<<gt, NTH>>>(WQ, wqth, wqtl);
    tsplit_kernel<<<gt, NTH>>>(WK, wkth, wktl);
    prefill_kernel<<<(NROWS * DM / 4 + NTH - 1) / NTH, NTH>>>(x, out, NROWS * DM / 4);

    // 1) M^T = scale * Wk^T Wq  (512x512)
    dim3 gm(DM / BN, DM / BM);
    mgemm_kernel<<<gm, NTH, SMEM_TOTAL>>>();

    // 2) G = x M (scale folded), V = x Wv^T (transposed)
    dim3 g1(DM / BN, NROWS / BM, 2);
    proj_kernel<<<g1, NTH, SMEM_TOTAL>>>();

    // 3) causal scores S = G x^T; masked tiles zero-filled
    dim3 g2(SEQ / BN, SEQ / BM, BSZ);
    scores_kernel<<<g2, NTH, SMEM_TOTAL>>>(att);

    // 4) softmax: fp32 probs to d_out, bf16 hi/lo probs to scratch
    softmax_kernel<<<NROWS, NTH>>>(att);

    // 5) O += P @ V  (split-K, 4 segments of <=32 chunks, atomic accumulate)
    dim3 g4(DM / BN, (SEQ / BM) * 4, BSZ);
    av_kernel<<<g4, NTH, SMEM_TOTAL>>>(out);
}